// round 1
// baseline (speedup 1.0000x reference)
#include <cuda_runtime.h>
#include <math.h>

// ---------------- problem constants ----------------
#define NN      16384      // nodes
#define EE      131072     // edges
#define HH      256        // hidden
#define LL      4          // GAT layers
#define GB      256        // graphs (batch)
#define NPG     64         // nodes per graph
#define NHEADS  8
#define DKH     32         // dk per head
#define DEG     8
#define FFD     512

// ---------------- scratch (device globals; allocation-free) ----------------
__device__ float g_h[NN * HH];
__device__ float g_m[NN * HH];
__device__ float g_q[NN * HH];
__device__ float g_k[NN * HH];
__device__ float g_v[NN * HH];
__device__ float g_o[NN * HH];
__device__ float g_ffb[NN * FFD];
__device__ float g_as[NN];
__device__ float g_ad[NN];
__device__ float g_gs[NN];
__device__ float g_wa[LL * 32];
__device__ float g_cb[LL];

// ---------------- generic tiled fp32 GEMM: C = act(A@W + bias) ----------------
// A: [M,K] row-major, W: [K,Nout] row-major, C: [M,Nout].
// BM=64, BN=64, BK=16, 256 threads, 4x4 per-thread tile.
// act: 0 = none, 1 = relu, 2 = gelu(exact erf)
#define BM 64
#define BN 64
#define BKK 16

__global__ __launch_bounds__(256) void gemm_kernel(
    const float* __restrict__ A, const float* __restrict__ W,
    const float* __restrict__ bias, float* __restrict__ C,
    int M, int K, int Nout, int act)
{
    __shared__ float As[BKK][BM];
    __shared__ float Bs[BKK][BN];

    const int tid = threadIdx.x;
    const int tx = tid & 15;        // 0..15 -> n
    const int ty = tid >> 4;        // 0..15 -> m
    const int m0 = blockIdx.y * BM;
    const int n0 = blockIdx.x * BN;

    const int la_m = tid >> 2;          // 0..63
    const int la_k = (tid & 3) * 4;     // 0,4,8,12
    const int lb_k = tid >> 4;          // 0..15
    const int lb_n = (tid & 15) * 4;    // 0..60

    float acc[4][4];
#pragma unroll
    for (int i = 0; i < 4; i++)
#pragma unroll
        for (int j = 0; j < 4; j++) acc[i][j] = 0.f;

    const int ty4 = ty * 4;
    const int tx4 = tx * 4;

    for (int k0 = 0; k0 < K; k0 += BKK) {
        float4 av = *(const float4*)&A[(size_t)(m0 + la_m) * K + k0 + la_k];
        As[la_k + 0][la_m] = av.x;
        As[la_k + 1][la_m] = av.y;
        As[la_k + 2][la_m] = av.z;
        As[la_k + 3][la_m] = av.w;
        *(float4*)&Bs[lb_k][lb_n] =
            *(const float4*)&W[(size_t)(k0 + lb_k) * Nout + n0 + lb_n];
        __syncthreads();

#pragma unroll
        for (int k = 0; k < BKK; k++) {
            float a0 = As[k][ty4 + 0];
            float a1 = As[k][ty4 + 1];
            float a2 = As[k][ty4 + 2];
            float a3 = As[k][ty4 + 3];
            float4 bv = *(const float4*)&Bs[k][tx4];
            acc[0][0] += a0 * bv.x; acc[0][1] += a0 * bv.y;
            acc[0][2] += a0 * bv.z; acc[0][3] += a0 * bv.w;
            acc[1][0] += a1 * bv.x; acc[1][1] += a1 * bv.y;
            acc[1][2] += a1 * bv.z; acc[1][3] += a1 * bv.w;
            acc[2][0] += a2 * bv.x; acc[2][1] += a2 * bv.y;
            acc[2][2] += a2 * bv.z; acc[2][3] += a2 * bv.w;
            acc[3][0] += a3 * bv.x; acc[3][1] += a3 * bv.y;
            acc[3][2] += a3 * bv.z; acc[3][3] += a3 * bv.w;
        }
        __syncthreads();
    }

    float bsv[4] = {0.f, 0.f, 0.f, 0.f};
    if (bias) {
#pragma unroll
        for (int j = 0; j < 4; j++) bsv[j] = bias[n0 + tx4 + j];
    }

#pragma unroll
    for (int i = 0; i < 4; i++) {
        float4 ov;
        float v[4];
#pragma unroll
        for (int j = 0; j < 4; j++) {
            float x = acc[i][j] + bsv[j];
            if (act == 1) x = fmaxf(x, 0.f);
            else if (act == 2) x = 0.5f * x * (1.f + erff(x * 0.70710678118654752f));
            v[j] = x;
        }
        ov.x = v[0]; ov.y = v[1]; ov.z = v[2]; ov.w = v[3];
        *(float4*)&C[(size_t)(m0 + ty4 + i) * Nout + n0 + tx4] = ov;
    }
}

// ---------------- fold edge projection into per-layer 32-dim vector ----------------
// g_wa[l][k] = sum_j We[k][j] * a_l[512+j];  g_cb[l] = sum_j be[j] * a_l[512+j]
__global__ void wa_kernel(const float* __restrict__ We, const float* __restrict__ be,
                          const float* __restrict__ gat_a)
{
    int l = blockIdx.x;
    int t = threadIdx.x;
    const float* a = gat_a + l * (3 * HH) + 2 * HH;
    if (t < 32) {
        float s = 0.f;
        const float* row = We + t * HH;
        for (int j = 0; j < HH; j++) s += row[j] * a[j];
        g_wa[l * 32 + t] = s;
    } else if (t == 32) {
        float s = 0.f;
        for (int j = 0; j < HH; j++) s += be[j] * a[j];
        g_cb[l] = s;
    }
}

// ---------------- per-node alpha_src / alpha_dst: warp per node ----------------
__global__ __launch_bounds__(256) void alpha_kernel(const float* __restrict__ gat_a, int l)
{
    int warp = threadIdx.x >> 5, lane = threadIdx.x & 31;
    int n = blockIdx.x * 8 + warp;
    const float* a = gat_a + l * (3 * HH);
    const float* mrow = g_m + (size_t)n * HH;
    float s = 0.f, d = 0.f;
#pragma unroll
    for (int j = lane; j < HH; j += 32) {
        float mv = mrow[j];
        s += mv * a[j];
        d += mv * a[HH + j];
    }
#pragma unroll
    for (int off = 16; off; off >>= 1) {
        s += __shfl_xor_sync(0xffffffffu, s, off);
        d += __shfl_xor_sync(0xffffffffu, d, off);
    }
    if (lane == 0) { g_as[n] = s; g_ad[n] = d; }
}

// ---------------- fused GAT node update: logits -> softmax(8) -> agg -> +res -> LN ----
__global__ __launch_bounds__(256) void gat_update_kernel(
    const int* __restrict__ dst, const float* __restrict__ edge_feats,
    const float* __restrict__ lng, const float* __restrict__ lnb, int l)
{
    __shared__ float lg[DEG];
    __shared__ int   sd[DEG];
    __shared__ float rs[8], rs2[8];

    int n = blockIdx.x;
    int t = threadIdx.x;
    int warp = t >> 5, lane = t & 31;

    if (t < DEG) {
        int eid = n * DEG + t;
        int d = dst[eid];
        const float* ef = edge_feats + (size_t)eid * 32;
        const float* wa = g_wa + l * 32;
        float ce = g_cb[l];
#pragma unroll
        for (int j = 0; j < 32; j++) ce += ef[j] * wa[j];
        float x = g_as[n] + g_ad[d] + ce;
        lg[t] = (x >= 0.f) ? x : 0.01f * x;   // LeakyReLU
        sd[t] = d;
    }
    __syncthreads();

    // local softmax over 8 edges (redundant per-thread, broadcast LDS)
    float mx = -1e30f;
#pragma unroll
    for (int k = 0; k < DEG; k++) mx = fmaxf(mx, lg[k]);
    float w[DEG]; float wsum = 0.f;
#pragma unroll
    for (int k = 0; k < DEG; k++) { w[k] = __expf(lg[k] - mx); wsum += w[k]; }
    float inv = 1.f / wsum;

    // aggregate: column t of the 8 gathered m rows (coalesced across threads)
    float acc = 0.f;
#pragma unroll
    for (int k = 0; k < DEG; k++) acc += (w[k] * inv) * g_m[(size_t)sd[k] * HH + t];

    float x = acc + g_h[(size_t)n * HH + t];

    // LayerNorm over 256 dims
    float s = x, s2 = x * x;
#pragma unroll
    for (int off = 16; off; off >>= 1) {
        s  += __shfl_xor_sync(0xffffffffu, s,  off);
        s2 += __shfl_xor_sync(0xffffffffu, s2, off);
    }
    if (lane == 0) { rs[warp] = s; rs2[warp] = s2; }
    __syncthreads();
    if (warp == 0) {
        float a = (lane < 8) ? rs[lane]  : 0.f;
        float b = (lane < 8) ? rs2[lane] : 0.f;
#pragma unroll
        for (int off = 4; off; off >>= 1) {
            a += __shfl_xor_sync(0xffffffffu, a, off);
            b += __shfl_xor_sync(0xffffffffu, b, off);
        }
        if (lane == 0) { rs[0] = a; rs2[0] = b; }
    }
    __syncthreads();
    float mean = rs[0] * (1.f / HH);
    float var  = rs2[0] * (1.f / HH) - mean * mean;
    float y = (x - mean) * rsqrtf(var + 1e-5f) * lng[l * HH + t] + lnb[l * HH + t];
    g_h[(size_t)n * HH + t] = y;
}

// ---------------- generic residual + LayerNorm: out = LN(xa+xb) ----------------
__global__ __launch_bounds__(256) void ln_kernel(
    const float* __restrict__ xa, const float* __restrict__ xb,
    const float* __restrict__ g, const float* __restrict__ b,
    float* __restrict__ out, float eps)
{
    __shared__ float rs[8], rs2[8];
    int n = blockIdx.x;
    int t = threadIdx.x;
    int warp = t >> 5, lane = t & 31;
    float x = xa[(size_t)n * HH + t] + xb[(size_t)n * HH + t];
    float s = x, s2 = x * x;
#pragma unroll
    for (int off = 16; off; off >>= 1) {
        s  += __shfl_xor_sync(0xffffffffu, s,  off);
        s2 += __shfl_xor_sync(0xffffffffu, s2, off);
    }
    if (lane == 0) { rs[warp] = s; rs2[warp] = s2; }
    __syncthreads();
    if (warp == 0) {
        float a = (lane < 8) ? rs[lane]  : 0.f;
        float c = (lane < 8) ? rs2[lane] : 0.f;
#pragma unroll
        for (int off = 4; off; off >>= 1) {
            a += __shfl_xor_sync(0xffffffffu, a, off);
            c += __shfl_xor_sync(0xffffffffu, c, off);
        }
        if (lane == 0) { rs[0] = a; rs2[0] = c; }
    }
    __syncthreads();
    float mean = rs[0] * (1.f / HH);
    float var  = rs2[0] * (1.f / HH) - mean * mean;
    out[(size_t)n * HH + t] = (x - mean) * rsqrtf(var + eps) * g[t] + b[t];
}

// ---------------- per-(graph, head) global attention ----------------
__global__ __launch_bounds__(256) void attn_kernel()
{
    __shared__ float qs[NPG][33];
    __shared__ float ks[NPG][33];
    __shared__ float vs[NPG][DKH];
    __shared__ float pb[8][NPG];

    int head = blockIdx.x;
    int b = blockIdx.y;
    int t = threadIdx.x;
    int warp = t >> 5, lane = t & 31;

    for (int idx = t; idx < NPG * DKH; idx += 256) {
        int r = idx >> 5, d = idx & 31;
        size_t g = (size_t)(b * NPG + r) * HH + head * DKH + d;
        qs[r][d] = g_q[g];
        ks[r][d] = g_k[g];
        vs[r][d] = g_v[g];
    }
    __syncthreads();

    const float scale = 0.17677669529663687f;   // 1/sqrt(32)
    for (int r = 0; r < 8; r++) {
        int i = warp * 8 + r;
        float s0 = 0.f, s1 = 0.f;
#pragma unroll
        for (int d = 0; d < DKH; d++) {
            float qd = qs[i][d];
            s0 += qd * ks[lane][d];
            s1 += qd * ks[lane + 32][d];
        }
        s0 *= scale; s1 *= scale;
        float mx = fmaxf(s0, s1);
#pragma unroll
        for (int off = 16; off; off >>= 1)
            mx = fmaxf(mx, __shfl_xor_sync(0xffffffffu, mx, off));
        float e0 = __expf(s0 - mx), e1 = __expf(s1 - mx);
        float sm = e0 + e1;
#pragma unroll
        for (int off = 16; off; off >>= 1)
            sm += __shfl_xor_sync(0xffffffffu, sm, off);
        float inv = 1.f / sm;
        pb[warp][lane] = e0 * inv;
        pb[warp][lane + 32] = e1 * inv;
        __syncwarp();
        float o = 0.f;
#pragma unroll
        for (int j = 0; j < NPG; j++) o += pb[warp][j] * vs[j][lane];
        g_o[(size_t)(b * NPG + i) * HH + head * DKH + lane] = o;
    }
}

// ---------------- gating scalar per node: warp per node ----------------
__global__ __launch_bounds__(256) void gvec_kernel(const float* __restrict__ gW2,
                                                   const float* __restrict__ gb2)
{
    int warp = threadIdx.x >> 5, lane = threadIdx.x & 31;
    int n = blockIdx.x * 8 + warp;
    const float* row = g_m + (size_t)n * HH;
    float s = 0.f;
#pragma unroll
    for (int j = lane; j < HH; j += 32) s += row[j] * gW2[j];
#pragma unroll
    for (int off = 16; off; off >>= 1) s += __shfl_xor_sync(0xffffffffu, s, off);
    if (lane == 0) g_gs[n] = s + gb2[0];
}

// ---------------- gated readout per graph ----------------
__global__ __launch_bounds__(256) void readout_kernel(float* __restrict__ out)
{
    __shared__ float p[NPG];
    int b = blockIdx.x;
    int t = threadIdx.x;
    if (t < NPG) p[t] = g_gs[b * NPG + t];
    __syncthreads();
    float mx = -1e30f;
#pragma unroll
    for (int i = 0; i < NPG; i++) mx = fmaxf(mx, p[i]);
    float s = 0.f, acc = 0.f;
    for (int i = 0; i < NPG; i++) {
        float w = __expf(p[i] - mx);
        s += w;
        acc += w * g_h[(size_t)(b * NPG + i) * HH + t];
    }
    out[b * HH + t] = acc / s;
}

// ---------------- host launcher ----------------
extern "C" void kernel_launch(void* const* d_in, const int* in_sizes, int n_in,
                              void* d_out, int out_size)
{
    const float* node_feats = (const float*)d_in[0];
    const float* edge_feats = (const float*)d_in[1];
    const int*   dst        = (const int*)  d_in[3];
    const float* Wn   = (const float*)d_in[4];
    const float* bn   = (const float*)d_in[5];
    const float* We   = (const float*)d_in[6];
    const float* be   = (const float*)d_in[7];
    const float* gatW = (const float*)d_in[8];
    const float* gata = (const float*)d_in[9];
    const float* glng = (const float*)d_in[10];
    const float* glnb = (const float*)d_in[11];
    const float* Wq   = (const float*)d_in[12];
    const float* Wk   = (const float*)d_in[13];
    const float* Wv   = (const float*)d_in[14];
    const float* alng = (const float*)d_in[15];
    const float* alnb = (const float*)d_in[16];
    const float* fW1  = (const float*)d_in[17];
    const float* fb1  = (const float*)d_in[18];
    const float* fW2  = (const float*)d_in[19];
    const float* fb2  = (const float*)d_in[20];
    const float* flng = (const float*)d_in[21];
    const float* flnb = (const float*)d_in[22];
    const float* gW1  = (const float*)d_in[23];
    const float* gb1  = (const float*)d_in[24];
    const float* gW2  = (const float*)d_in[25];
    const float* gb2  = (const float*)d_in[26];
    float* out = (float*)d_out;

    float *h_p, *m_p, *q_p, *k_p, *v_p, *o_p, *ff_p;
    cudaGetSymbolAddress((void**)&h_p, g_h);
    cudaGetSymbolAddress((void**)&m_p, g_m);
    cudaGetSymbolAddress((void**)&q_p, g_q);
    cudaGetSymbolAddress((void**)&k_p, g_k);
    cudaGetSymbolAddress((void**)&v_p, g_v);
    cudaGetSymbolAddress((void**)&o_p, g_o);
    cudaGetSymbolAddress((void**)&ff_p, g_ffb);

    dim3 gH(HH / BN, NN / BM);       // (4, 256)
    dim3 gF(FFD / BN, NN / BM);      // (8, 256)

    // input projection: h = node_feats @ Wn + bn
    gemm_kernel<<<gH, 256>>>(node_feats, Wn, bn, h_p, NN, 64, HH, 0);
    // folded edge-projection vectors for all layers
    wa_kernel<<<LL, 64>>>(We, be, gata);

    for (int l = 0; l < LL; l++) {
        gemm_kernel<<<gH, 256>>>(h_p, gatW + (size_t)l * HH * HH, nullptr, m_p, NN, HH, HH, 0);
        alpha_kernel<<<NN / 8, 256>>>(gata, l);
        gat_update_kernel<<<NN, 256>>>(dst, edge_feats, glng, glnb, l);
    }

    // global attention
    gemm_kernel<<<gH, 256>>>(h_p, Wq, nullptr, q_p, NN, HH, HH, 0);
    gemm_kernel<<<gH, 256>>>(h_p, Wk, nullptr, k_p, NN, HH, HH, 0);
    gemm_kernel<<<gH, 256>>>(h_p, Wv, nullptr, v_p, NN, HH, HH, 0);
    attn_kernel<<<dim3(NHEADS, GB), 256>>>();
    ln_kernel<<<NN, 256>>>(o_p, h_p, alng, alnb, h_p, 1e-6f);

    // feed-forward
    gemm_kernel<<<gF, 256>>>(h_p, fW1, fb1, ff_p, NN, HH, FFD, 2);
    gemm_kernel<<<gH, 256>>>(ff_p, fW2, fb2, m_p, NN, FFD, HH, 0);
    ln_kernel<<<NN, 256>>>(h_p, m_p, flng, flnb, h_p, 1e-6f);

    // gating readout
    gemm_kernel<<<gH, 256>>>(h_p, gW1, gb1, m_p, NN, HH, HH, 1);
    gvec_kernel<<<NN / 8, 256>>>(gW2, gb2);
    readout_kernel<<<GB, 256>>>(out);

    (void)in_sizes; (void)n_in; (void)out_size;
}

// round 2
// speedup vs baseline: 1.5621x; 1.5621x over previous
#include <cuda_runtime.h>
#include <cuda_bf16.h>
#include <math.h>
#include <stdint.h>

// ---------------- problem constants ----------------
#define NN      16384      // nodes
#define EE      131072     // edges
#define HH      256        // hidden
#define LL      4          // GAT layers
#define GB      256        // graphs
#define NPG     64         // nodes per graph
#define NHEADS  8
#define DKH     32
#define DEG     8
#define FFD     512

// ---------------- fp32 scratch ----------------
__device__ float g_h[NN * HH];
__device__ float g_m[NN * HH];
__device__ float g_q[NN * HH];
__device__ float g_k[NN * HH];
__device__ float g_v[NN * HH];
__device__ float g_o[NN * HH];
__device__ float g_as[NN];
__device__ float g_ad[NN];
__device__ float g_gs[NN];
__device__ float g_wa[LL * 32];
__device__ float g_cb[LL];

// ---------------- bf16 hi/lo scratch (activations) ----------------
__device__ __nv_bfloat16 g_nf_h[NN * 64],   g_nf_l[NN * 64];
__device__ __nv_bfloat16 g_h_h[NN * HH],    g_h_l[NN * HH];
__device__ __nv_bfloat16 g_ff_h[NN * FFD],  g_ff_l[NN * FFD];

// ---------------- bf16 hi/lo weights, transposed to [N][K] ----------------
__device__ __nv_bfloat16 g_wnt_h[HH * 64],        g_wnt_l[HH * 64];
__device__ __nv_bfloat16 g_gatwt_h[LL * HH * HH], g_gatwt_l[LL * HH * HH];
__device__ __nv_bfloat16 g_wqt_h[HH * HH],  g_wqt_l[HH * HH];
__device__ __nv_bfloat16 g_wkt_h[HH * HH],  g_wkt_l[HH * HH];
__device__ __nv_bfloat16 g_wvt_h[HH * HH],  g_wvt_l[HH * HH];
__device__ __nv_bfloat16 g_ff1t_h[FFD * HH], g_ff1t_l[FFD * HH];
__device__ __nv_bfloat16 g_ff2t_h[HH * FFD], g_ff2t_l[HH * FFD];
__device__ __nv_bfloat16 g_gw1t_h[HH * HH],  g_gw1t_l[HH * HH];

// ================= conversion kernel: fp32 -> (bf16 hi, bf16 lo), opt transpose ====
struct ConvEnt {
    const float* src;
    __nv_bfloat16* hi;
    __nv_bfloat16* lo;
    int K, N, trans, blk0, nblk;
};
struct ConvTab { ConvEnt e[13]; int n; };

__global__ __launch_bounds__(256) void conv_kernel(ConvTab tab)
{
    int b = blockIdx.x;
    int ei = 0;
    for (int i = 0; i < tab.n; i++)
        if (b >= tab.e[i].blk0) ei = i;
    ConvEnt e = tab.e[ei];
    int lb = b - e.blk0;
    int total = e.K * e.N;
    int base = lb * 1024;
#pragma unroll
    for (int j = 0; j < 4; j++) {
        int i = base + j * 256 + threadIdx.x;
        if (i < total) {
            float x = e.src[i];
            __nv_bfloat16 h = __float2bfloat16_rn(x);
            __nv_bfloat16 l = __float2bfloat16_rn(x - __bfloat162float(h));
            int di;
            if (e.trans) { int k = i / e.N, n = i % e.N; di = n * e.K + k; }
            else di = i;
            e.hi[di] = h;
            e.lo[di] = l;
        }
    }
}

// ================= tensor-core GEMM: C = act(A@W^T + bias) ==========
// A: [M][K] as bf16 hi/lo, W^T: [Nout][K] as bf16 hi/lo.
// BM=128, BN=128, BK=16, 256 thr (8 warps, 2m x 4n), warp tile 64x32.
// act: 0 none, 1 relu, 2 gelu. Optional fp32 C and bf16 hi/lo C outputs.
#define SA 18

__device__ __forceinline__ void mma_bf16(float* c, const uint32_t* a,
                                         uint32_t b0, uint32_t b1)
{
    asm volatile(
        "mma.sync.aligned.m16n8k16.row.col.f32.bf16.bf16.f32 "
        "{%0,%1,%2,%3}, {%4,%5,%6,%7}, {%8,%9}, {%0,%1,%2,%3};\n"
        : "+f"(c[0]), "+f"(c[1]), "+f"(c[2]), "+f"(c[3])
        : "r"(a[0]), "r"(a[1]), "r"(a[2]), "r"(a[3]), "r"(b0), "r"(b1));
}

__global__ __launch_bounds__(256, 2) void gemm_tc(
    const __nv_bfloat16* __restrict__ Ah, const __nv_bfloat16* __restrict__ Al,
    const __nv_bfloat16* __restrict__ Bh, const __nv_bfloat16* __restrict__ Bl,
    const float* __restrict__ bias,
    float* __restrict__ Cf,
    __nv_bfloat16* __restrict__ Chi, __nv_bfloat16* __restrict__ Clo,
    int M, int K, int Nout, int act)
{
    __shared__ __nv_bfloat16 sAh[128 * SA];
    __shared__ __nv_bfloat16 sAl[128 * SA];
    __shared__ __nv_bfloat16 sBh[128 * SA];
    __shared__ __nv_bfloat16 sBl[128 * SA];

    const int t = threadIdx.x;
    const int warp = t >> 5, lane = t & 31;
    const int wm = (warp & 1) * 64;
    const int wn = (warp >> 1) * 32;
    const int r = lane >> 2, c2 = (lane & 3) * 2;
    const int m0 = blockIdx.y * 128;
    const int n0 = blockIdx.x * 128;

    const int tr = t >> 1;
    const int tk = (t & 1) * 8;

    float acc[4][4][4];
#pragma unroll
    for (int i = 0; i < 4; i++)
#pragma unroll
        for (int j = 0; j < 4; j++)
#pragma unroll
            for (int k = 0; k < 4; k++) acc[i][j][k] = 0.f;

    const size_t arow = (size_t)(m0 + tr) * K + tk;
    const size_t brow = (size_t)(n0 + tr) * K + tk;
    uint32_t* sAhw = (uint32_t*)&sAh[tr * SA + tk];
    uint32_t* sAlw = (uint32_t*)&sAl[tr * SA + tk];
    uint32_t* sBhw = (uint32_t*)&sBh[tr * SA + tk];
    uint32_t* sBlw = (uint32_t*)&sBl[tr * SA + tk];

    for (int k0 = 0; k0 < K; k0 += 16) {
        uint4 va  = *(const uint4*)(Ah + arow + k0);
        uint4 val = *(const uint4*)(Al + arow + k0);
        uint4 vb  = *(const uint4*)(Bh + brow + k0);
        uint4 vbl = *(const uint4*)(Bl + brow + k0);
        sAhw[0] = va.x;  sAhw[1] = va.y;  sAhw[2] = va.z;  sAhw[3] = va.w;
        sAlw[0] = val.x; sAlw[1] = val.y; sAlw[2] = val.z; sAlw[3] = val.w;
        sBhw[0] = vb.x;  sBhw[1] = vb.y;  sBhw[2] = vb.z;  sBhw[3] = vb.w;
        sBlw[0] = vbl.x; sBlw[1] = vbl.y; sBlw[2] = vbl.z; sBlw[3] = vbl.w;
        __syncthreads();

        uint32_t ah[4][4], al[4][4];
#pragma unroll
        for (int mt = 0; mt < 4; mt++) {
            int rb = (wm + mt * 16 + r) * SA;
            ah[mt][0] = *(const uint32_t*)&sAh[rb + c2];
            ah[mt][1] = *(const uint32_t*)&sAh[rb + 8 * SA + c2];
            ah[mt][2] = *(const uint32_t*)&sAh[rb + c2 + 8];
            ah[mt][3] = *(const uint32_t*)&sAh[rb + 8 * SA + c2 + 8];
            al[mt][0] = *(const uint32_t*)&sAl[rb + c2];
            al[mt][1] = *(const uint32_t*)&sAl[rb + 8 * SA + c2];
            al[mt][2] = *(const uint32_t*)&sAl[rb + c2 + 8];
            al[mt][3] = *(const uint32_t*)&sAl[rb + 8 * SA + c2 + 8];
        }
#pragma unroll
        for (int nt = 0; nt < 4; nt++) {
            int nb = (wn + nt * 8 + r) * SA;
            uint32_t bh0 = *(const uint32_t*)&sBh[nb + c2];
            uint32_t bh1 = *(const uint32_t*)&sBh[nb + c2 + 8];
            uint32_t bl0 = *(const uint32_t*)&sBl[nb + c2];
            uint32_t bl1 = *(const uint32_t*)&sBl[nb + c2 + 8];
#pragma unroll
            for (int mt = 0; mt < 4; mt++) {
                mma_bf16(acc[mt][nt], ah[mt], bh0, bh1);
                mma_bf16(acc[mt][nt], al[mt], bh0, bh1);
                mma_bf16(acc[mt][nt], ah[mt], bl0, bl1);
            }
        }
        __syncthreads();
    }

    // epilogue
#pragma unroll
    for (int nt = 0; nt < 4; nt++) {
        int col = n0 + wn + nt * 8 + c2;
        float b0 = bias ? bias[col] : 0.f;
        float b1 = bias ? bias[col + 1] : 0.f;
#pragma unroll
        for (int mt = 0; mt < 4; mt++) {
            int row = m0 + wm + mt * 16 + r;
#pragma unroll
            for (int half = 0; half < 2; half++) {
                int rr = row + half * 8;
                float v0 = acc[mt][nt][half * 2 + 0] + b0;
                float v1 = acc[mt][nt][half * 2 + 1] + b1;
                if (act == 1) { v0 = fmaxf(v0, 0.f); v1 = fmaxf(v1, 0.f); }
                else if (act == 2) {
                    v0 = 0.5f * v0 * (1.f + erff(v0 * 0.70710678118654752f));
                    v1 = 0.5f * v1 * (1.f + erff(v1 * 0.70710678118654752f));
                }
                size_t o = (size_t)rr * Nout + col;
                if (Cf) *(float2*)(Cf + o) = make_float2(v0, v1);
                if (Chi) {
                    __nv_bfloat16 h0 = __float2bfloat16_rn(v0);
                    __nv_bfloat16 h1 = __float2bfloat16_rn(v1);
                    __nv_bfloat162 hp; hp.x = h0; hp.y = h1;
                    *(__nv_bfloat162*)(Chi + o) = hp;
                    __nv_bfloat162 lp;
                    lp.x = __float2bfloat16_rn(v0 - __bfloat162float(h0));
                    lp.y = __float2bfloat16_rn(v1 - __bfloat162float(h1));
                    *(__nv_bfloat162*)(Clo + o) = lp;
                }
            }
        }
    }
}

// ---------------- fold edge projection into per-layer 32-dim vector ----------------
__global__ void wa_kernel(const float* __restrict__ We, const float* __restrict__ be,
                          const float* __restrict__ gat_a)
{
    int l = blockIdx.x;
    int t = threadIdx.x;
    const float* a = gat_a + l * (3 * HH) + 2 * HH;
    if (t < 32) {
        float s = 0.f;
        const float* row = We + t * HH;
        for (int j = 0; j < HH; j++) s += row[j] * a[j];
        g_wa[l * 32 + t] = s;
    } else if (t == 32) {
        float s = 0.f;
        for (int j = 0; j < HH; j++) s += be[j] * a[j];
        g_cb[l] = s;
    }
}

// ---------------- per-node alpha_src / alpha_dst ----------------
__global__ __launch_bounds__(256) void alpha_kernel(const float* __restrict__ gat_a, int l)
{
    int warp = threadIdx.x >> 5, lane = threadIdx.x & 31;
    int n = blockIdx.x * 8 + warp;
    const float* a = gat_a + l * (3 * HH);
    const float* mrow = g_m + (size_t)n * HH;
    float s = 0.f, d = 0.f;
#pragma unroll
    for (int j = lane; j < HH; j += 32) {
        float mv = mrow[j];
        s += mv * a[j];
        d += mv * a[HH + j];
    }
#pragma unroll
    for (int off = 16; off; off >>= 1) {
        s += __shfl_xor_sync(0xffffffffu, s, off);
        d += __shfl_xor_sync(0xffffffffu, d, off);
    }
    if (lane == 0) { g_as[n] = s; g_ad[n] = d; }
}

// ---------------- fused GAT node update ----------------
__global__ __launch_bounds__(256) void gat_update_kernel(
    const int* __restrict__ dst, const float* __restrict__ edge_feats,
    const float* __restrict__ lng, const float* __restrict__ lnb, int l)
{
    __shared__ float lg[DEG];
    __shared__ int   sd[DEG];
    __shared__ float rs[8], rs2[8];

    int n = blockIdx.x;
    int t = threadIdx.x;
    int warp = t >> 5, lane = t & 31;

    if (t < DEG) {
        int eid = n * DEG + t;
        int d = dst[eid];
        const float* ef = edge_feats + (size_t)eid * 32;
        const float* wa = g_wa + l * 32;
        float ce = g_cb[l];
#pragma unroll
        for (int j = 0; j < 32; j++) ce += ef[j] * wa[j];
        float x = g_as[n] + g_ad[d] + ce;
        lg[t] = (x >= 0.f) ? x : 0.01f * x;
        sd[t] = d;
    }
    __syncthreads();

    float mx = -1e30f;
#pragma unroll
    for (int k = 0; k < DEG; k++) mx = fmaxf(mx, lg[k]);
    float w[DEG]; float wsum = 0.f;
#pragma unroll
    for (int k = 0; k < DEG; k++) { w[k] = __expf(lg[k] - mx); wsum += w[k]; }
    float inv = 1.f / wsum;

    float acc = 0.f;
#pragma unroll
    for (int k = 0; k < DEG; k++) acc += (w[k] * inv) * g_m[(size_t)sd[k] * HH + t];

    float x = acc + g_h[(size_t)n * HH + t];

    float s = x, s2 = x * x;
#pragma unroll
    for (int off = 16; off; off >>= 1) {
        s  += __shfl_xor_sync(0xffffffffu, s,  off);
        s2 += __shfl_xor_sync(0xffffffffu, s2, off);
    }
    if (lane == 0) { rs[warp] = s; rs2[warp] = s2; }
    __syncthreads();
    if (warp == 0) {
        float a = (lane < 8) ? rs[lane]  : 0.f;
        float b = (lane < 8) ? rs2[lane] : 0.f;
#pragma unroll
        for (int off = 4; off; off >>= 1) {
            a += __shfl_xor_sync(0xffffffffu, a, off);
            b += __shfl_xor_sync(0xffffffffu, b, off);
        }
        if (lane == 0) { rs[0] = a; rs2[0] = b; }
    }
    __syncthreads();
    float mean = rs[0] * (1.f / HH);
    float var  = rs2[0] * (1.f / HH) - mean * mean;
    float y = (x - mean) * rsqrtf(var + 1e-5f) * lng[l * HH + t] + lnb[l * HH + t];
    size_t o = (size_t)n * HH + t;
    g_h[o] = y;
    __nv_bfloat16 hh = __float2bfloat16_rn(y);
    g_h_h[o] = hh;
    g_h_l[o] = __float2bfloat16_rn(y - __bfloat162float(hh));
}

// ---------------- residual + LayerNorm (+ optional bf16 hi/lo out) ----------------
__global__ __launch_bounds__(256) void ln_kernel(
    const float* __restrict__ xa, const float* __restrict__ xb,
    const float* __restrict__ g, const float* __restrict__ b,
    float* __restrict__ out,
    __nv_bfloat16* __restrict__ ohi, __nv_bfloat16* __restrict__ olo,
    float eps)
{
    __shared__ float rs[8], rs2[8];
    int n = blockIdx.x;
    int t = threadIdx.x;
    int warp = t >> 5, lane = t & 31;
    float x = xa[(size_t)n * HH + t] + xb[(size_t)n * HH + t];
    float s = x, s2 = x * x;
#pragma unroll
    for (int off = 16; off; off >>= 1) {
        s  += __shfl_xor_sync(0xffffffffu, s,  off);
        s2 += __shfl_xor_sync(0xffffffffu, s2, off);
    }
    if (lane == 0) { rs[warp] = s; rs2[warp] = s2; }
    __syncthreads();
    if (warp == 0) {
        float a = (lane < 8) ? rs[lane]  : 0.f;
        float c = (lane < 8) ? rs2[lane] : 0.f;
#pragma unroll
        for (int off = 4; off; off >>= 1) {
            a += __shfl_xor_sync(0xffffffffu, a, off);
            c += __shfl_xor_sync(0xffffffffu, c, off);
        }
        if (lane == 0) { rs[0] = a; rs2[0] = c; }
    }
    __syncthreads();
    float mean = rs[0] * (1.f / HH);
    float var  = rs2[0] * (1.f / HH) - mean * mean;
    float y = (x - mean) * rsqrtf(var + eps) * g[t] + b[t];
    size_t o = (size_t)n * HH + t;
    out[o] = y;
    if (ohi) {
        __nv_bfloat16 hh = __float2bfloat16_rn(y);
        ohi[o] = hh;
        olo[o] = __float2bfloat16_rn(y - __bfloat162float(hh));
    }
}

// ---------------- per-(graph, head) global attention ----------------
__global__ __launch_bounds__(256) void attn_kernel()
{
    __shared__ float qs[NPG][33];
    __shared__ float ks[NPG][33];
    __shared__ float vs[NPG][DKH];
    __shared__ float pb[8][NPG];

    int head = blockIdx.x;
    int b = blockIdx.y;
    int t = threadIdx.x;
    int warp = t >> 5, lane = t & 31;

    for (int idx = t; idx < NPG * DKH; idx += 256) {
        int r = idx >> 5, d = idx & 31;
        size_t g = (size_t)(b * NPG + r) * HH + head * DKH + d;
        qs[r][d] = g_q[g];
        ks[r][d] = g_k[g];
        vs[r][d] = g_v[g];
    }
    __syncthreads();

    const float scale = 0.17677669529663687f;
    for (int r = 0; r < 8; r++) {
        int i = warp * 8 + r;
        float s0 = 0.f, s1 = 0.f;
#pragma unroll
        for (int d = 0; d < DKH; d++) {
            float qd = qs[i][d];
            s0 += qd * ks[lane][d];
            s1 += qd * ks[lane + 32][d];
        }
        s0 *= scale; s1 *= scale;
        float mx = fmaxf(s0, s1);
#pragma unroll
        for (int off = 16; off; off >>= 1)
            mx = fmaxf(mx, __shfl_xor_sync(0xffffffffu, mx, off));
        float e0 = __expf(s0 - mx), e1 = __expf(s1 - mx);
        float sm = e0 + e1;
#pragma unroll
        for (int off = 16; off; off >>= 1)
            sm += __shfl_xor_sync(0xffffffffu, sm, off);
        float inv = 1.f / sm;
        pb[warp][lane] = e0 * inv;
        pb[warp][lane + 32] = e1 * inv;
        __syncwarp();
        float o = 0.f;
#pragma unroll
        for (int j = 0; j < NPG; j++) o += pb[warp][j] * vs[j][lane];
        g_o[(size_t)(b * NPG + i) * HH + head * DKH + lane] = o;
    }
}

// ---------------- gating scalar per node ----------------
__global__ __launch_bounds__(256) void gvec_kernel(const float* __restrict__ gW2,
                                                   const float* __restrict__ gb2)
{
    int warp = threadIdx.x >> 5, lane = threadIdx.x & 31;
    int n = blockIdx.x * 8 + warp;
    const float* row = g_m + (size_t)n * HH;
    float s = 0.f;
#pragma unroll
    for (int j = lane; j < HH; j += 32) s += row[j] * gW2[j];
#pragma unroll
    for (int off = 16; off; off >>= 1) s += __shfl_xor_sync(0xffffffffu, s, off);
    if (lane == 0) g_gs[n] = s + gb2[0];
}

// ---------------- gated readout per graph ----------------
__global__ __launch_bounds__(256) void readout_kernel(float* __restrict__ out)
{
    __shared__ float p[NPG];
    int b = blockIdx.x;
    int t = threadIdx.x;
    if (t < NPG) p[t] = g_gs[b * NPG + t];
    __syncthreads();
    float mx = -1e30f;
#pragma unroll
    for (int i = 0; i < NPG; i++) mx = fmaxf(mx, p[i]);
    float s = 0.f, acc = 0.f;
    for (int i = 0; i < NPG; i++) {
        float w = __expf(p[i] - mx);
        s += w;
        acc += w * g_h[(size_t)(b * NPG + i) * HH + t];
    }
    out[b * HH + t] = acc / s;
}

// ---------------- host launcher ----------------
static inline __nv_bfloat16* sym(const void* s)
{
    void* p = nullptr;
    cudaGetSymbolAddress(&p, s);
    return (__nv_bfloat16*)p;
}

extern "C" void kernel_launch(void* const* d_in, const int* in_sizes, int n_in,
                              void* d_out, int out_size)
{
    const float* node_feats = (const float*)d_in[0];
    const float* edge_feats = (const float*)d_in[1];
    const int*   dst        = (const int*)  d_in[3];
    const float* Wn   = (const float*)d_in[4];
    const float* bn   = (const float*)d_in[5];
    const float* We   = (const float*)d_in[6];
    const float* be   = (const float*)d_in[7];
    const float* gatW = (const float*)d_in[8];
    const float* gata = (const float*)d_in[9];
    const float* glng = (const float*)d_in[10];
    const float* glnb = (const float*)d_in[11];
    const float* Wq   = (const float*)d_in[12];
    const float* Wk   = (const float*)d_in[13];
    const float* Wv   = (const float*)d_in[14];
    const float* alng = (const float*)d_in[15];
    const float* alnb = (const float*)d_in[16];
    const float* fW1  = (const float*)d_in[17];
    const float* fb1  = (const float*)d_in[18];
    const float* fW2  = (const float*)d_in[19];
    const float* fb2  = (const float*)d_in[20];
    const float* flng = (const float*)d_in[21];
    const float* flnb = (const float*)d_in[22];
    const float* gW1  = (const float*)d_in[23];
    const float* gb1  = (const float*)d_in[24];
    const float* gW2  = (const float*)d_in[25];
    const float* gb2  = (const float*)d_in[26];
    float* out = (float*)d_out;

    float *h_p, *m_p, *q_p, *k_p, *v_p, *o_p;
    cudaGetSymbolAddress((void**)&h_p, g_h);
    cudaGetSymbolAddress((void**)&m_p, g_m);
    cudaGetSymbolAddress((void**)&q_p, g_q);
    cudaGetSymbolAddress((void**)&k_p, g_k);
    cudaGetSymbolAddress((void**)&v_p, g_v);
    cudaGetSymbolAddress((void**)&o_p, g_o);

    __nv_bfloat16 *nf_h = sym(g_nf_h), *nf_l = sym(g_nf_l);
    __nv_bfloat16 *h_h = sym(g_h_h),  *h_l = sym(g_h_l);
    __nv_bfloat16 *ff_h = sym(g_ff_h), *ff_l = sym(g_ff_l);
    __nv_bfloat16 *wnt_h = sym(g_wnt_h), *wnt_l = sym(g_wnt_l);
    __nv_bfloat16 *gwt_h = sym(g_gatwt_h), *gwt_l = sym(g_gatwt_l);
    __nv_bfloat16 *wqt_h = sym(g_wqt_h), *wqt_l = sym(g_wqt_l);
    __nv_bfloat16 *wkt_h = sym(g_wkt_h), *wkt_l = sym(g_wkt_l);
    __nv_bfloat16 *wvt_h = sym(g_wvt_h), *wvt_l = sym(g_wvt_l);
    __nv_bfloat16 *f1t_h = sym(g_ff1t_h), *f1t_l = sym(g_ff1t_l);
    __nv_bfloat16 *f2t_h = sym(g_ff2t_h), *f2t_l = sym(g_ff2t_l);
    __nv_bfloat16 *g1t_h = sym(g_gw1t_h), *g1t_l = sym(g_gw1t_l);

    // ---- conversion table ----
    ConvTab tab;
    int ne = 0, blk = 0;
    auto add = [&](const float* s, __nv_bfloat16* hi, __nv_bfloat16* lo,
                   int K, int N, int tr) {
        int nb = (K * N + 1023) / 1024;
        tab.e[ne] = {s, hi, lo, K, N, tr, blk, nb};
        blk += nb; ne++;
    };
    add(Wn, wnt_h, wnt_l, 64, HH, 1);
    for (int l = 0; l < LL; l++)
        add(gatW + (size_t)l * HH * HH, gwt_h + (size_t)l * HH * HH,
            gwt_l + (size_t)l * HH * HH, HH, HH, 1);
    add(Wq, wqt_h, wqt_l, HH, HH, 1);
    add(Wk, wkt_h, wkt_l, HH, HH, 1);
    add(Wv, wvt_h, wvt_l, HH, HH, 1);
    add(fW1, f1t_h, f1t_l, HH, FFD, 1);
    add(fW2, f2t_h, f2t_l, FFD, HH, 1);
    add(gW1, g1t_h, g1t_l, HH, HH, 1);
    add(node_feats, nf_h, nf_l, NN, 64, 0);
    tab.n = ne;

    conv_kernel<<<blk, 256>>>(tab);
    wa_kernel<<<LL, 64>>>(We, be, gata);

    dim3 gH(HH / 128, NN / 128);    // (2, 128)
    dim3 gF(FFD / 128, NN / 128);   // (4, 128)

    // input projection: h = nf @ Wn + bn (fp32 + hi/lo)
    gemm_tc<<<gH, 256>>>(nf_h, nf_l, wnt_h, wnt_l, bn, h_p, h_h, h_l,
                         NN, 64, HH, 0);

    for (int l = 0; l < LL; l++) {
        gemm_tc<<<gH, 256>>>(h_h, h_l, gwt_h + (size_t)l * HH * HH,
                             gwt_l + (size_t)l * HH * HH, nullptr,
                             m_p, nullptr, nullptr, NN, HH, HH, 0);
        alpha_kernel<<<NN / 8, 256>>>(gata, l);
        gat_update_kernel<<<NN, 256>>>(dst, edge_feats, glng, glnb, l);
    }

    // global attention
    gemm_tc<<<gH, 256>>>(h_h, h_l, wqt_h, wqt_l, nullptr, q_p, nullptr, nullptr,
                         NN, HH, HH, 0);
    gemm_tc<<<gH, 256>>>(h_h, h_l, wkt_h, wkt_l, nullptr, k_p, nullptr, nullptr,
                         NN, HH, HH, 0);
    gemm_tc<<<gH, 256>>>(h_h, h_l, wvt_h, wvt_l, nullptr, v_p, nullptr, nullptr,
                         NN, HH, HH, 0);
    attn_kernel<<<dim3(NHEADS, GB), 256>>>();
    ln_kernel<<<NN, 256>>>(o_p, h_p, alng, alnb, h_p, h_h, h_l, 1e-6f);

    // feed-forward
    gemm_tc<<<gF, 256>>>(h_h, h_l, f1t_h, f1t_l, fb1, nullptr, ff_h, ff_l,
                         NN, HH, FFD, 2);
    gemm_tc<<<gH, 256>>>(ff_h, ff_l, f2t_h, f2t_l, fb2, m_p, nullptr, nullptr,
                         NN, FFD, HH, 0);
    ln_kernel<<<NN, 256>>>(h_p, m_p, flng, flnb, h_p, h_h, h_l, 1e-6f);

    // gating readout
    gemm_tc<<<gH, 256>>>(h_h, h_l, g1t_h, g1t_l, gb1, m_p, nullptr, nullptr,
                         NN, HH, HH, 1);
    gvec_kernel<<<NN / 8, 256>>>(gW2, gb2);
    readout_kernel<<<GB, 256>>>(out);

    (void)in_sizes; (void)n_in; (void)out_size;
}

// round 3
// speedup vs baseline: 1.7070x; 1.0928x over previous
#include <cuda_runtime.h>
#include <cuda_bf16.h>
#include <math.h>
#include <stdint.h>

// ---------------- problem constants ----------------
#define NN      16384
#define EE      131072
#define HH      256
#define LL      4
#define GB      256
#define NPG     64
#define NHEADS  8
#define DKH     32
#define DEG     8
#define FFD     512

// ---------------- fp32 scratch ----------------
__device__ float g_h[NN * HH];
__device__ float g_m[NN * HH];
__device__ float g_qkv[NN * 768];
__device__ float g_o[NN * HH];
__device__ float g_as[NN];
__device__ float g_ad[NN];
__device__ float g_gs[NN];
__device__ float g_wa[LL * 32];
__device__ float g_cb[LL];

// ---------------- bf16 hi/lo scratch (activations) ----------------
__device__ __nv_bfloat16 g_nf_h[NN * 64],   g_nf_l[NN * 64];
__device__ __nv_bfloat16 g_h_h[NN * HH],    g_h_l[NN * HH];
__device__ __nv_bfloat16 g_ff_h[NN * FFD],  g_ff_l[NN * FFD];

// ---------------- bf16 hi/lo weights, transposed to [N][K] ----------------
__device__ __nv_bfloat16 g_wnt_h[HH * 64],        g_wnt_l[HH * 64];
__device__ __nv_bfloat16 g_gatwt_h[LL * HH * HH], g_gatwt_l[LL * HH * HH];
__device__ __nv_bfloat16 g_qkvt_h[768 * HH], g_qkvt_l[768 * HH];
__device__ __nv_bfloat16 g_ff1t_h[FFD * HH], g_ff1t_l[FFD * HH];
__device__ __nv_bfloat16 g_ff2t_h[HH * FFD], g_ff2t_l[HH * FFD];
__device__ __nv_bfloat16 g_gw1t_h[HH * HH],  g_gw1t_l[HH * HH];

// ================= conversion: fp32 -> (bf16 hi, lo), optional transpose =========
struct ConvEnt {
    const float* src;
    __nv_bfloat16* hi;
    __nv_bfloat16* lo;
    int K, N, trans, blk0, nblk;
};
struct ConvTab { ConvEnt e[13]; int n; };

__global__ __launch_bounds__(256) void conv_kernel(ConvTab tab)
{
    int b = blockIdx.x;
    int ei = 0;
    for (int i = 0; i < tab.n; i++)
        if (b >= tab.e[i].blk0) ei = i;
    ConvEnt e = tab.e[ei];
    int lb = b - e.blk0;
    int total = e.K * e.N;
    int base = lb * 1024;
#pragma unroll
    for (int j = 0; j < 4; j++) {
        int i = base + j * 256 + threadIdx.x;
        if (i < total) {
            float x = e.src[i];
            __nv_bfloat16 h = __float2bfloat16_rn(x);
            __nv_bfloat16 l = __float2bfloat16_rn(x - __bfloat162float(h));
            int di;
            if (e.trans) { int k = i / e.N, n = i % e.N; di = n * e.K + k; }
            else di = i;
            e.hi[di] = h;
            e.lo[di] = l;
        }
    }
}

// ================= pipelined tensor-core GEMM =====================
// C = act(A@W^T + bias). A:[M][K] bf16 hi/lo, W^T:[Nout][K] bf16 hi/lo.
// BM=128, BN=128, BK=16, 2-stage cp.async pipeline, 8 warps (2m x 4n),
// warp tile 64x32, 3 MMAs per fragment (hi*hi + lo*hi + hi*lo).
#define SA 24   // row pad: conflict-free and 16B-aligned

__device__ __forceinline__ void mma_bf16(float* c, const uint32_t* a,
                                         uint32_t b0, uint32_t b1)
{
    asm volatile(
        "mma.sync.aligned.m16n8k16.row.col.f32.bf16.bf16.f32 "
        "{%0,%1,%2,%3}, {%4,%5,%6,%7}, {%8,%9}, {%0,%1,%2,%3};\n"
        : "+f"(c[0]), "+f"(c[1]), "+f"(c[2]), "+f"(c[3])
        : "r"(a[0]), "r"(a[1]), "r"(a[2]), "r"(a[3]), "r"(b0), "r"(b1));
}

__device__ __forceinline__ void cp16(void* s, const void* g)
{
    uint32_t sa = (uint32_t)__cvta_generic_to_shared(s);
    asm volatile("cp.async.ca.shared.global [%0], [%1], 16;\n" :: "r"(sa), "l"(g));
}

__global__ __launch_bounds__(256, 2) void gemm_tc(
    const __nv_bfloat16* __restrict__ Ah, const __nv_bfloat16* __restrict__ Al,
    const __nv_bfloat16* __restrict__ Bh, const __nv_bfloat16* __restrict__ Bl,
    const float* __restrict__ bias,
    float* __restrict__ Cf,
    __nv_bfloat16* __restrict__ Chi, __nv_bfloat16* __restrict__ Clo,
    int M, int K, int Nout, int act)
{
    __shared__ __nv_bfloat16 sAh[2][128 * SA];
    __shared__ __nv_bfloat16 sAl[2][128 * SA];
    __shared__ __nv_bfloat16 sBh[2][128 * SA];
    __shared__ __nv_bfloat16 sBl[2][128 * SA];

    const int t = threadIdx.x;
    const int warp = t >> 5, lane = t & 31;
    const int wm = (warp & 1) * 64;
    const int wn = (warp >> 1) * 32;
    const int r = lane >> 2, c2 = (lane & 3) * 2;
    const int m0 = blockIdx.y * 128;
    const int n0 = blockIdx.x * 128;

    const int tr = t >> 1;
    const int tk = (t & 1) * 8;
    const int so = tr * SA + tk;

    float acc[4][4][4];
#pragma unroll
    for (int i = 0; i < 4; i++)
#pragma unroll
        for (int j = 0; j < 4; j++)
#pragma unroll
            for (int k = 0; k < 4; k++) acc[i][j][k] = 0.f;

    const __nv_bfloat16* pAh = Ah + (size_t)(m0 + tr) * K + tk;
    const __nv_bfloat16* pAl = Al + (size_t)(m0 + tr) * K + tk;
    const __nv_bfloat16* pBh = Bh + (size_t)(n0 + tr) * K + tk;
    const __nv_bfloat16* pBl = Bl + (size_t)(n0 + tr) * K + tk;

    // prefetch stage 0
    cp16(&sAh[0][so], pAh);
    cp16(&sAl[0][so], pAl);
    cp16(&sBh[0][so], pBh);
    cp16(&sBl[0][so], pBl);
    asm volatile("cp.async.commit_group;\n");

    const int nIter = K >> 4;
    for (int i = 0; i < nIter; i++) {
        const int s = i & 1;
        if (i + 1 < nIter) {
            int k0 = (i + 1) << 4;
            int ns = (i + 1) & 1;
            cp16(&sAh[ns][so], pAh + k0);
            cp16(&sAl[ns][so], pAl + k0);
            cp16(&sBh[ns][so], pBh + k0);
            cp16(&sBl[ns][so], pBl + k0);
            asm volatile("cp.async.commit_group;\n");
            asm volatile("cp.async.wait_group 1;\n");
        } else {
            asm volatile("cp.async.wait_group 0;\n");
        }
        __syncthreads();

        uint32_t ah[4][4], al[4][4];
#pragma unroll
        for (int mt = 0; mt < 4; mt++) {
            int rb = (wm + mt * 16 + r) * SA;
            ah[mt][0] = *(const uint32_t*)&sAh[s][rb + c2];
            ah[mt][1] = *(const uint32_t*)&sAh[s][rb + 8 * SA + c2];
            ah[mt][2] = *(const uint32_t*)&sAh[s][rb + c2 + 8];
            ah[mt][3] = *(const uint32_t*)&sAh[s][rb + 8 * SA + c2 + 8];
            al[mt][0] = *(const uint32_t*)&sAl[s][rb + c2];
            al[mt][1] = *(const uint32_t*)&sAl[s][rb + 8 * SA + c2];
            al[mt][2] = *(const uint32_t*)&sAl[s][rb + c2 + 8];
            al[mt][3] = *(const uint32_t*)&sAl[s][rb + 8 * SA + c2 + 8];
        }
#pragma unroll
        for (int nt = 0; nt < 4; nt++) {
            int nb = (wn + nt * 8 + r) * SA;
            uint32_t bh0 = *(const uint32_t*)&sBh[s][nb + c2];
            uint32_t bh1 = *(const uint32_t*)&sBh[s][nb + c2 + 8];
            uint32_t bl0 = *(const uint32_t*)&sBl[s][nb + c2];
            uint32_t bl1 = *(const uint32_t*)&sBl[s][nb + c2 + 8];
#pragma unroll
            for (int mt = 0; mt < 4; mt++) {
                mma_bf16(acc[mt][nt], ah[mt], bh0, bh1);
                mma_bf16(acc[mt][nt], al[mt], bh0, bh1);
                mma_bf16(acc[mt][nt], ah[mt], bl0, bl1);
            }
        }
        __syncthreads();
    }

    // epilogue
#pragma unroll
    for (int nt = 0; nt < 4; nt++) {
        int col = n0 + wn + nt * 8 + c2;
        float b0 = bias ? bias[col] : 0.f;
        float b1 = bias ? bias[col + 1] : 0.f;
#pragma unroll
        for (int mt = 0; mt < 4; mt++) {
            int row = m0 + wm + mt * 16 + r;
#pragma unroll
            for (int half = 0; half < 2; half++) {
                int rr = row + half * 8;
                float v0 = acc[mt][nt][half * 2 + 0] + b0;
                float v1 = acc[mt][nt][half * 2 + 1] + b1;
                if (act == 1) { v0 = fmaxf(v0, 0.f); v1 = fmaxf(v1, 0.f); }
                else if (act == 2) {
                    v0 = 0.5f * v0 * (1.f + erff(v0 * 0.70710678118654752f));
                    v1 = 0.5f * v1 * (1.f + erff(v1 * 0.70710678118654752f));
                }
                size_t o = (size_t)rr * Nout + col;
                if (Cf) *(float2*)(Cf + o) = make_float2(v0, v1);
                if (Chi) {
                    __nv_bfloat16 h0 = __float2bfloat16_rn(v0);
                    __nv_bfloat16 h1 = __float2bfloat16_rn(v1);
                    __nv_bfloat162 hp; hp.x = h0; hp.y = h1;
                    *(__nv_bfloat162*)(Chi + o) = hp;
                    __nv_bfloat162 lp;
                    lp.x = __float2bfloat16_rn(v0 - __bfloat162float(h0));
                    lp.y = __float2bfloat16_rn(v1 - __bfloat162float(h1));
                    *(__nv_bfloat162*)(Clo + o) = lp;
                }
            }
        }
    }
}

// ---------------- fold edge projection into per-layer 32-dim vector ----------------
__global__ void wa_kernel(const float* __restrict__ We, const float* __restrict__ be,
                          const float* __restrict__ gat_a)
{
    int l = blockIdx.x;
    int t = threadIdx.x;
    const float* a = gat_a + l * (3 * HH) + 2 * HH;
    if (t < 32) {
        float s = 0.f;
        const float* row = We + t * HH;
        for (int j = 0; j < HH; j++) s += row[j] * a[j];
        g_wa[l * 32 + t] = s;
    } else if (t == 32) {
        float s = 0.f;
        for (int j = 0; j < HH; j++) s += be[j] * a[j];
        g_cb[l] = s;
    }
}

// ---------------- per-node alpha_src / alpha_dst ----------------
__global__ __launch_bounds__(256) void alpha_kernel(const float* __restrict__ gat_a, int l)
{
    int warp = threadIdx.x >> 5, lane = threadIdx.x & 31;
    int n = blockIdx.x * 8 + warp;
    const float* a = gat_a + l * (3 * HH);
    const float* mrow = g_m + (size_t)n * HH;
    float s = 0.f, d = 0.f;
#pragma unroll
    for (int j = lane; j < HH; j += 32) {
        float mv = mrow[j];
        s += mv * a[j];
        d += mv * a[HH + j];
    }
#pragma unroll
    for (int off = 16; off; off >>= 1) {
        s += __shfl_xor_sync(0xffffffffu, s, off);
        d += __shfl_xor_sync(0xffffffffu, d, off);
    }
    if (lane == 0) { g_as[n] = s; g_ad[n] = d; }
}

// ---------------- fused GAT node update ----------------
__global__ __launch_bounds__(256) void gat_update_kernel(
    const int* __restrict__ dst, const float* __restrict__ edge_feats,
    const float* __restrict__ lng, const float* __restrict__ lnb, int l)
{
    __shared__ float lg[DEG];
    __shared__ int   sd[DEG];
    __shared__ float rs[8], rs2[8];

    int n = blockIdx.x;
    int t = threadIdx.x;
    int warp = t >> 5, lane = t & 31;

    if (t < DEG) {
        int eid = n * DEG + t;
        int d = dst[eid];
        const float* ef = edge_feats + (size_t)eid * 32;
        const float* wa = g_wa + l * 32;
        float ce = g_cb[l];
#pragma unroll
        for (int j = 0; j < 32; j++) ce += ef[j] * wa[j];
        float x = g_as[n] + g_ad[d] + ce;
        lg[t] = (x >= 0.f) ? x : 0.01f * x;
        sd[t] = d;
    }
    __syncthreads();

    float mx = -1e30f;
#pragma unroll
    for (int k = 0; k < DEG; k++) mx = fmaxf(mx, lg[k]);
    float w[DEG]; float wsum = 0.f;
#pragma unroll
    for (int k = 0; k < DEG; k++) { w[k] = __expf(lg[k] - mx); wsum += w[k]; }
    float inv = 1.f / wsum;

    float acc = 0.f;
#pragma unroll
    for (int k = 0; k < DEG; k++) acc += (w[k] * inv) * g_m[(size_t)sd[k] * HH + t];

    float x = acc + g_h[(size_t)n * HH + t];

    float s = x, s2 = x * x;
#pragma unroll
    for (int off = 16; off; off >>= 1) {
        s  += __shfl_xor_sync(0xffffffffu, s,  off);
        s2 += __shfl_xor_sync(0xffffffffu, s2, off);
    }
    if (lane == 0) { rs[warp] = s; rs2[warp] = s2; }
    __syncthreads();
    if (warp == 0) {
        float a = (lane < 8) ? rs[lane]  : 0.f;
        float b = (lane < 8) ? rs2[lane] : 0.f;
#pragma unroll
        for (int off = 4; off; off >>= 1) {
            a += __shfl_xor_sync(0xffffffffu, a, off);
            b += __shfl_xor_sync(0xffffffffu, b, off);
        }
        if (lane == 0) { rs[0] = a; rs2[0] = b; }
    }
    __syncthreads();
    float mean = rs[0] * (1.f / HH);
    float var  = rs2[0] * (1.f / HH) - mean * mean;
    float y = (x - mean) * rsqrtf(var + 1e-5f) * lng[l * HH + t] + lnb[l * HH + t];
    size_t o = (size_t)n * HH + t;
    g_h[o] = y;
    __nv_bfloat16 hh = __float2bfloat16_rn(y);
    g_h_h[o] = hh;
    g_h_l[o] = __float2bfloat16_rn(y - __bfloat162float(hh));
}

// ---------------- residual + LayerNorm (+ optional bf16 hi/lo out) ----------------
__global__ __launch_bounds__(256) void ln_kernel(
    const float* __restrict__ xa, const float* __restrict__ xb,
    const float* __restrict__ g, const float* __restrict__ b,
    float* __restrict__ out,
    __nv_bfloat16* __restrict__ ohi, __nv_bfloat16* __restrict__ olo,
    float eps)
{
    __shared__ float rs[8], rs2[8];
    int n = blockIdx.x;
    int t = threadIdx.x;
    int warp = t >> 5, lane = t & 31;
    float x = xa[(size_t)n * HH + t] + xb[(size_t)n * HH + t];
    float s = x, s2 = x * x;
#pragma unroll
    for (int off = 16; off; off >>= 1) {
        s  += __shfl_xor_sync(0xffffffffu, s,  off);
        s2 += __shfl_xor_sync(0xffffffffu, s2, off);
    }
    if (lane == 0) { rs[warp] = s; rs2[warp] = s2; }
    __syncthreads();
    if (warp == 0) {
        float a = (lane < 8) ? rs[lane]  : 0.f;
        float c = (lane < 8) ? rs2[lane] : 0.f;
#pragma unroll
        for (int off = 4; off; off >>= 1) {
            a += __shfl_xor_sync(0xffffffffu, a, off);
            c += __shfl_xor_sync(0xffffffffu, c, off);
        }
        if (lane == 0) { rs[0] = a; rs2[0] = c; }
    }
    __syncthreads();
    float mean = rs[0] * (1.f / HH);
    float var  = rs2[0] * (1.f / HH) - mean * mean;
    float y = (x - mean) * rsqrtf(var + eps) * g[t] + b[t];
    size_t o = (size_t)n * HH + t;
    out[o] = y;
    if (ohi) {
        __nv_bfloat16 hh = __float2bfloat16_rn(y);
        ohi[o] = hh;
        olo[o] = __float2bfloat16_rn(y - __bfloat162float(hh));
    }
}

// ---------------- per-(graph, head) global attention (packed qkv) ----------------
__global__ __launch_bounds__(256) void attn_kernel()
{
    __shared__ float qs[NPG][33];
    __shared__ float ks[NPG][33];
    __shared__ float vs[NPG][DKH];
    __shared__ float pb[8][NPG];

    int head = blockIdx.x;
    int b = blockIdx.y;
    int t = threadIdx.x;
    int warp = t >> 5, lane = t & 31;

    for (int idx = t; idx < NPG * DKH; idx += 256) {
        int r = idx >> 5, d = idx & 31;
        size_t g = (size_t)(b * NPG + r) * 768 + head * DKH + d;
        qs[r][d] = g_qkv[g];
        ks[r][d] = g_qkv[g + 256];
        vs[r][d] = g_qkv[g + 512];
    }
    __syncthreads();

    const float scale = 0.17677669529663687f;
    for (int r = 0; r < 8; r++) {
        int i = warp * 8 + r;
        float s0 = 0.f, s1 = 0.f;
#pragma unroll
        for (int d = 0; d < DKH; d++) {
            float qd = qs[i][d];
            s0 += qd * ks[lane][d];
            s1 += qd * ks[lane + 32][d];
        }
        s0 *= scale; s1 *= scale;
        float mx = fmaxf(s0, s1);
#pragma unroll
        for (int off = 16; off; off >>= 1)
            mx = fmaxf(mx, __shfl_xor_sync(0xffffffffu, mx, off));
        float e0 = __expf(s0 - mx), e1 = __expf(s1 - mx);
        float sm = e0 + e1;
#pragma unroll
        for (int off = 16; off; off >>= 1)
            sm += __shfl_xor_sync(0xffffffffu, sm, off);
        float inv = 1.f / sm;
        pb[warp][lane] = e0 * inv;
        pb[warp][lane + 32] = e1 * inv;
        __syncwarp();
        float o = 0.f;
#pragma unroll
        for (int j = 0; j < NPG; j++) o += pb[warp][j] * vs[j][lane];
        g_o[(size_t)(b * NPG + i) * HH + head * DKH + lane] = o;
    }
}

// ---------------- gating scalar per node ----------------
__global__ __launch_bounds__(256) void gvec_kernel(const float* __restrict__ gW2,
                                                   const float* __restrict__ gb2)
{
    int warp = threadIdx.x >> 5, lane = threadIdx.x & 31;
    int n = blockIdx.x * 8 + warp;
    const float* row = g_m + (size_t)n * HH;
    float s = 0.f;
#pragma unroll
    for (int j = lane; j < HH; j += 32) s += row[j] * gW2[j];
#pragma unroll
    for (int off = 16; off; off >>= 1) s += __shfl_xor_sync(0xffffffffu, s, off);
    if (lane == 0) g_gs[n] = s + gb2[0];
}

// ---------------- gated readout per graph ----------------
__global__ __launch_bounds__(256) void readout_kernel(float* __restrict__ out)
{
    __shared__ float p[NPG];
    int b = blockIdx.x;
    int t = threadIdx.x;
    if (t < NPG) p[t] = g_gs[b * NPG + t];
    __syncthreads();
    float mx = -1e30f;
#pragma unroll
    for (int i = 0; i < NPG; i++) mx = fmaxf(mx, p[i]);
    float s = 0.f, acc = 0.f;
    for (int i = 0; i < NPG; i++) {
        float w = __expf(p[i] - mx);
        s += w;
        acc += w * g_h[(size_t)(b * NPG + i) * HH + t];
    }
    out[b * HH + t] = acc / s;
}

// ---------------- host launcher ----------------
static inline __nv_bfloat16* sym(const void* s)
{
    void* p = nullptr;
    cudaGetSymbolAddress(&p, s);
    return (__nv_bfloat16*)p;
}

extern "C" void kernel_launch(void* const* d_in, const int* in_sizes, int n_in,
                              void* d_out, int out_size)
{
    const float* node_feats = (const float*)d_in[0];
    const float* edge_feats = (const float*)d_in[1];
    const int*   dst        = (const int*)  d_in[3];
    const float* Wn   = (const float*)d_in[4];
    const float* bn   = (const float*)d_in[5];
    const float* We   = (const float*)d_in[6];
    const float* be   = (const float*)d_in[7];
    const float* gatW = (const float*)d_in[8];
    const float* gata = (const float*)d_in[9];
    const float* glng = (const float*)d_in[10];
    const float* glnb = (const float*)d_in[11];
    const float* Wq   = (const float*)d_in[12];
    const float* Wk   = (const float*)d_in[13];
    const float* Wv   = (const float*)d_in[14];
    const float* alng = (const float*)d_in[15];
    const float* alnb = (const float*)d_in[16];
    const float* fW1  = (const float*)d_in[17];
    const float* fb1  = (const float*)d_in[18];
    const float* fW2  = (const float*)d_in[19];
    const float* fb2  = (const float*)d_in[20];
    const float* flng = (const float*)d_in[21];
    const float* flnb = (const float*)d_in[22];
    const float* gW1  = (const float*)d_in[23];
    const float* gb1  = (const float*)d_in[24];
    const float* gW2  = (const float*)d_in[25];
    const float* gb2  = (const float*)d_in[26];
    float* out = (float*)d_out;

    float *h_p, *m_p, *qkv_p, *o_p;
    cudaGetSymbolAddress((void**)&h_p, g_h);
    cudaGetSymbolAddress((void**)&m_p, g_m);
    cudaGetSymbolAddress((void**)&qkv_p, g_qkv);
    cudaGetSymbolAddress((void**)&o_p, g_o);

    __nv_bfloat16 *nf_h = sym(g_nf_h), *nf_l = sym(g_nf_l);
    __nv_bfloat16 *h_h = sym(g_h_h),  *h_l = sym(g_h_l);
    __nv_bfloat16 *ff_h = sym(g_ff_h), *ff_l = sym(g_ff_l);
    __nv_bfloat16 *wnt_h = sym(g_wnt_h), *wnt_l = sym(g_wnt_l);
    __nv_bfloat16 *gwt_h = sym(g_gatwt_h), *gwt_l = sym(g_gatwt_l);
    __nv_bfloat16 *qkvt_h = sym(g_qkvt_h), *qkvt_l = sym(g_qkvt_l);
    __nv_bfloat16 *f1t_h = sym(g_ff1t_h), *f1t_l = sym(g_ff1t_l);
    __nv_bfloat16 *f2t_h = sym(g_ff2t_h), *f2t_l = sym(g_ff2t_l);
    __nv_bfloat16 *g1t_h = sym(g_gw1t_h), *g1t_l = sym(g_gw1t_l);

    ConvTab tab;
    int ne = 0, blk = 0;
    auto add = [&](const float* s, __nv_bfloat16* hi, __nv_bfloat16* lo,
                   int K, int N, int tr) {
        int nb = (K * N + 1023) / 1024;
        tab.e[ne] = {s, hi, lo, K, N, tr, blk, nb};
        blk += nb; ne++;
    };
    add(Wn, wnt_h, wnt_l, 64, HH, 1);
    for (int l = 0; l < LL; l++)
        add(gatW + (size_t)l * HH * HH, gwt_h + (size_t)l * HH * HH,
            gwt_l + (size_t)l * HH * HH, HH, HH, 1);
    add(Wq, qkvt_h, qkvt_l, HH, HH, 1);
    add(Wk, qkvt_h + 256 * HH, qkvt_l + 256 * HH, HH, HH, 1);
    add(Wv, qkvt_h + 512 * HH, qkvt_l + 512 * HH, HH, HH, 1);
    add(fW1, f1t_h, f1t_l, HH, FFD, 1);
    add(fW2, f2t_h, f2t_l, FFD, HH, 1);
    add(gW1, g1t_h, g1t_l, HH, HH, 1);
    add(node_feats, nf_h, nf_l, NN, 64, 0);
    tab.n = ne;

    conv_kernel<<<blk, 256>>>(tab);
    wa_kernel<<<LL, 64>>>(We, be, gata);

    dim3 gH(HH / 128, NN / 128);     // (2, 128)
    dim3 gQKV(768 / 128, NN / 128);  // (6, 128)
    dim3 gF(FFD / 128, NN / 128);    // (4, 128)

    gemm_tc<<<gH, 256>>>(nf_h, nf_l, wnt_h, wnt_l, bn, h_p, h_h, h_l,
                         NN, 64, HH, 0);

    for (int l = 0; l < LL; l++) {
        gemm_tc<<<gH, 256>>>(h_h, h_l, gwt_h + (size_t)l * HH * HH,
                             gwt_l + (size_t)l * HH * HH, nullptr,
                             m_p, nullptr, nullptr, NN, HH, HH, 0);
        alpha_kernel<<<NN / 8, 256>>>(gata, l);
        gat_update_kernel<<<NN, 256>>>(dst, edge_feats, glng, glnb, l);
    }

    // fused QKV projection
    gemm_tc<<<gQKV, 256>>>(h_h, h_l, qkvt_h, qkvt_l, nullptr, qkv_p,
                           nullptr, nullptr, NN, HH, 768, 0);
    attn_kernel<<<dim3(NHEADS, GB), 256>>>();
    ln_kernel<<<NN, 256>>>(o_p, h_p, alng, alnb, h_p, h_h, h_l, 1e-6f);

    // feed-forward
    gemm_tc<<<gF, 256>>>(h_h, h_l, f1t_h, f1t_l, fb1, nullptr, ff_h, ff_l,
                         NN, HH, FFD, 2);
    gemm_tc<<<gH, 256>>>(ff_h, ff_l, f2t_h, f2t_l, fb2, m_p, nullptr, nullptr,
                         NN, FFD, HH, 0);
    ln_kernel<<<NN, 256>>>(h_p, m_p, flng, flnb, h_p, h_h, h_l, 1e-6f);

    // gating readout
    gemm_tc<<<gH, 256>>>(h_h, h_l, g1t_h, g1t_l, gb1, m_p, nullptr, nullptr,
                         NN, HH, HH, 1);
    gvec_kernel<<<NN / 8, 256>>>(gW2, gb2);
    readout_kernel<<<GB, 256>>>(out);

    (void)in_sizes; (void)n_in; (void)out_size;
}

// round 4
// speedup vs baseline: 1.8649x; 1.0925x over previous
#include <cuda_runtime.h>
#include <cuda_bf16.h>
#include <math.h>
#include <stdint.h>

// ---------------- problem constants ----------------
#define NN      16384
#define EE      131072
#define HH      256
#define LL      4
#define GB      256
#define NPG     64
#define NHEADS  8
#define DKH     32
#define DEG     8
#define FFD     512

// ---------------- fp32 scratch ----------------
__device__ float g_h[NN * HH];
__device__ float g_m[NN * HH];
__device__ float g_qkv[NN * 768];
__device__ float g_o[NN * HH];
__device__ float g_as[NN];
__device__ float g_ad[NN];
__device__ float g_gs[NN];
__device__ float g_wa[LL * 32];
__device__ float g_cb[LL];

// ---------------- bf16 hi/lo scratch (activations) ----------------
__device__ __nv_bfloat16 g_nf_h[NN * 64],   g_nf_l[NN * 64];
__device__ __nv_bfloat16 g_h_h[NN * HH],    g_h_l[NN * HH];
__device__ __nv_bfloat16 g_ff_h[NN * FFD],  g_ff_l[NN * FFD];

// ---------------- bf16 hi/lo weights, transposed to [N][K] ----------------
__device__ __nv_bfloat16 g_wnt_h[HH * 64],        g_wnt_l[HH * 64];
__device__ __nv_bfloat16 g_gatwt_h[LL * HH * HH], g_gatwt_l[LL * HH * HH];
__device__ __nv_bfloat16 g_qkvt_h[768 * HH], g_qkvt_l[768 * HH];
__device__ __nv_bfloat16 g_ff1t_h[FFD * HH], g_ff1t_l[FFD * HH];
__device__ __nv_bfloat16 g_ff2t_h[HH * FFD], g_ff2t_l[HH * FFD];
__device__ __nv_bfloat16 g_gw1t_h[HH * HH],  g_gw1t_l[HH * HH];

// ================= conversion: fp32 -> (bf16 hi, lo), optional transpose =========
struct ConvEnt {
    const float* src;
    __nv_bfloat16* hi;
    __nv_bfloat16* lo;
    int K, N, trans, blk0, nblk;
};
struct ConvTab { ConvEnt e[13]; int n; };

__global__ __launch_bounds__(256) void conv_kernel(ConvTab tab)
{
    int b = blockIdx.x;
    int ei = 0;
    for (int i = 0; i < tab.n; i++)
        if (b >= tab.e[i].blk0) ei = i;
    ConvEnt e = tab.e[ei];
    int lb = b - e.blk0;
    int total = e.K * e.N;
    int base = lb * 1024;
#pragma unroll
    for (int j = 0; j < 4; j++) {
        int i = base + j * 256 + threadIdx.x;
        if (i < total) {
            float x = e.src[i];
            __nv_bfloat16 h = __float2bfloat16_rn(x);
            __nv_bfloat16 l = __float2bfloat16_rn(x - __bfloat162float(h));
            int di;
            if (e.trans) { int k = i / e.N, n = i % e.N; di = n * e.K + k; }
            else di = i;
            e.hi[di] = h;
            e.lo[di] = l;
        }
    }
}

// ================= pipelined tensor-core GEMM (ldmatrix, BK=32) ==========
// C = act(A@W^T + bias). A:[M][K] bf16 hi/lo, W^T:[Nout][K] bf16 hi/lo.
// BM=128, BN=128, BK=32, 2-stage cp.async, 8 warps (2m x 4n), warp 64x32.
#define SA   40                 // padded row stride (elements); conflict-free
#define BUFE (128 * SA)         // 5120 elements per buffer per stage
#define SMEM_GEMM (8 * BUFE * 2) // 2 stages * 4 buffers * 10240 B = 81920

__device__ __forceinline__ void mma_bf16(float* c, const uint32_t* a,
                                         uint32_t b0, uint32_t b1)
{
    asm volatile(
        "mma.sync.aligned.m16n8k16.row.col.f32.bf16.bf16.f32 "
        "{%0,%1,%2,%3}, {%4,%5,%6,%7}, {%8,%9}, {%0,%1,%2,%3};\n"
        : "+f"(c[0]), "+f"(c[1]), "+f"(c[2]), "+f"(c[3])
        : "r"(a[0]), "r"(a[1]), "r"(a[2]), "r"(a[3]), "r"(b0), "r"(b1));
}

__device__ __forceinline__ void cp16(void* s, const void* g)
{
    uint32_t sa = (uint32_t)__cvta_generic_to_shared(s);
    asm volatile("cp.async.ca.shared.global [%0], [%1], 16;\n" :: "r"(sa), "l"(g));
}

__device__ __forceinline__ void ldmat4(uint32_t& r0, uint32_t& r1,
                                       uint32_t& r2, uint32_t& r3, uint32_t addr)
{
    asm volatile("ldmatrix.sync.aligned.m8n8.x4.shared.b16 {%0,%1,%2,%3}, [%4];\n"
                 : "=r"(r0), "=r"(r1), "=r"(r2), "=r"(r3) : "r"(addr));
}

__global__ __launch_bounds__(256, 2) void gemm_tc(
    const __nv_bfloat16* __restrict__ Ah, const __nv_bfloat16* __restrict__ Al,
    const __nv_bfloat16* __restrict__ Bh, const __nv_bfloat16* __restrict__ Bl,
    const float* __restrict__ bias,
    float* __restrict__ Cf,
    __nv_bfloat16* __restrict__ Chi, __nv_bfloat16* __restrict__ Clo,
    int M, int K, int Nout, int act)
{
    extern __shared__ __nv_bfloat16 sm[];
    __nv_bfloat16* sAh = sm;
    __nv_bfloat16* sAl = sm + 2 * BUFE;
    __nv_bfloat16* sBh = sm + 4 * BUFE;
    __nv_bfloat16* sBl = sm + 6 * BUFE;

    const int t = threadIdx.x;
    const int warp = t >> 5, lane = t & 31;
    const int wm = (warp & 1) * 64;
    const int wn = (warp >> 1) * 32;
    const int r = lane >> 2, c2 = (lane & 3) * 2;
    const int m0 = blockIdx.y * 128;
    const int n0 = blockIdx.x * 128;

    // cp.async loader indices: thread -> (row lr & lr+64, 8-elt chunk lc)
    const int lr = t >> 2;
    const int lc = (t & 3) * 8;

    // ldmatrix per-lane tile offsets
    const int g8 = lane >> 3;
    const int lrow = (g8 & 1) * 8 + (lane & 7);   // row within 16-row tile
    const int kof = (g8 >> 1) * 8;                // k offset within 16-k slice

    float acc[4][4][4];
#pragma unroll
    for (int i = 0; i < 4; i++)
#pragma unroll
        for (int j = 0; j < 4; j++)
#pragma unroll
            for (int k = 0; k < 4; k++) acc[i][j][k] = 0.f;

    const __nv_bfloat16* pAh = Ah + (size_t)(m0 + lr) * K + lc;
    const __nv_bfloat16* pAl = Al + (size_t)(m0 + lr) * K + lc;
    const __nv_bfloat16* pBh = Bh + (size_t)(n0 + lr) * K + lc;
    const __nv_bfloat16* pBl = Bl + (size_t)(n0 + lr) * K + lc;
    const size_t rs64 = (size_t)64 * K;

    const int so0 = lr * SA + lc;
    const int so1 = (lr + 64) * SA + lc;

    uint32_t bAh = (uint32_t)__cvta_generic_to_shared(sAh);
    uint32_t bAl = (uint32_t)__cvta_generic_to_shared(sAl);
    uint32_t bBh = (uint32_t)__cvta_generic_to_shared(sBh);
    uint32_t bBl = (uint32_t)__cvta_generic_to_shared(sBl);

    // prefetch stage 0
    cp16(&sAh[so0], pAh);            cp16(&sAh[so1], pAh + rs64);
    cp16(&sAl[so0], pAl);            cp16(&sAl[so1], pAl + rs64);
    cp16(&sBh[so0], pBh);            cp16(&sBh[so1], pBh + rs64);
    cp16(&sBl[so0], pBl);            cp16(&sBl[so1], pBl + rs64);
    asm volatile("cp.async.commit_group;\n");

    const int nIter = K >> 5;
    for (int i = 0; i < nIter; i++) {
        const int s = i & 1;
        if (i + 1 < nIter) {
            int k0 = (i + 1) << 5;
            int nso = ((i + 1) & 1) * BUFE;
            cp16(&sAh[nso + so0], pAh + k0);  cp16(&sAh[nso + so1], pAh + rs64 + k0);
            cp16(&sAl[nso + so0], pAl + k0);  cp16(&sAl[nso + so1], pAl + rs64 + k0);
            cp16(&sBh[nso + so0], pBh + k0);  cp16(&sBh[nso + so1], pBh + rs64 + k0);
            cp16(&sBl[nso + so0], pBl + k0);  cp16(&sBl[nso + so1], pBl + rs64 + k0);
            asm volatile("cp.async.commit_group;\n");
            asm volatile("cp.async.wait_group 1;\n");
        } else {
            asm volatile("cp.async.wait_group 0;\n");
        }
        __syncthreads();

        const uint32_t sb = s * BUFE * 2;   // byte offset of stage
#pragma unroll
        for (int ks = 0; ks < 2; ks++) {
            uint32_t ah[4][4], al[4][4];
#pragma unroll
            for (int mt = 0; mt < 4; mt++) {
                uint32_t off = ((wm + mt * 16 + lrow) * SA + ks * 16 + kof) * 2;
                ldmat4(ah[mt][0], ah[mt][1], ah[mt][2], ah[mt][3], bAh + sb + off);
                ldmat4(al[mt][0], al[mt][1], al[mt][2], al[mt][3], bAl + sb + off);
            }
#pragma unroll
            for (int ntp = 0; ntp < 2; ntp++) {
                uint32_t off = ((wn + ntp * 16 + lrow) * SA + ks * 16 + kof) * 2;
                uint32_t h0, h1, h2, h3, l0, l1, l2, l3;
                ldmat4(h0, h1, h2, h3, bBh + sb + off);
                ldmat4(l0, l1, l2, l3, bBl + sb + off);
#pragma unroll
                for (int mt = 0; mt < 4; mt++) {
                    mma_bf16(acc[mt][2 * ntp],     ah[mt], h0, h2);
                    mma_bf16(acc[mt][2 * ntp],     al[mt], h0, h2);
                    mma_bf16(acc[mt][2 * ntp],     ah[mt], l0, l2);
                    mma_bf16(acc[mt][2 * ntp + 1], ah[mt], h1, h3);
                    mma_bf16(acc[mt][2 * ntp + 1], al[mt], h1, h3);
                    mma_bf16(acc[mt][2 * ntp + 1], ah[mt], l1, l3);
                }
            }
        }
        __syncthreads();
    }

    // epilogue
#pragma unroll
    for (int nt = 0; nt < 4; nt++) {
        int col = n0 + wn + nt * 8 + c2;
        float b0 = bias ? bias[col] : 0.f;
        float b1 = bias ? bias[col + 1] : 0.f;
#pragma unroll
        for (int mt = 0; mt < 4; mt++) {
            int row = m0 + wm + mt * 16 + r;
#pragma unroll
            for (int half = 0; half < 2; half++) {
                int rr = row + half * 8;
                float v0 = acc[mt][nt][half * 2 + 0] + b0;
                float v1 = acc[mt][nt][half * 2 + 1] + b1;
                if (act == 1) { v0 = fmaxf(v0, 0.f); v1 = fmaxf(v1, 0.f); }
                else if (act == 2) {
                    v0 = 0.5f * v0 * (1.f + erff(v0 * 0.70710678118654752f));
                    v1 = 0.5f * v1 * (1.f + erff(v1 * 0.70710678118654752f));
                }
                size_t o = (size_t)rr * Nout + col;
                if (Cf) *(float2*)(Cf + o) = make_float2(v0, v1);
                if (Chi) {
                    __nv_bfloat16 h0 = __float2bfloat16_rn(v0);
                    __nv_bfloat16 h1 = __float2bfloat16_rn(v1);
                    __nv_bfloat162 hp; hp.x = h0; hp.y = h1;
                    *(__nv_bfloat162*)(Chi + o) = hp;
                    __nv_bfloat162 lp;
                    lp.x = __float2bfloat16_rn(v0 - __bfloat162float(h0));
                    lp.y = __float2bfloat16_rn(v1 - __bfloat162float(h1));
                    *(__nv_bfloat162*)(Clo + o) = lp;
                }
            }
        }
    }
}

// ---------------- fold edge projection into per-layer 32-dim vector ----------------
__global__ void wa_kernel(const float* __restrict__ We, const float* __restrict__ be,
                          const float* __restrict__ gat_a)
{
    int l = blockIdx.x;
    int t = threadIdx.x;
    const float* a = gat_a + l * (3 * HH) + 2 * HH;
    if (t < 32) {
        float s = 0.f;
        const float* row = We + t * HH;
        for (int j = 0; j < HH; j++) s += row[j] * a[j];
        g_wa[l * 32 + t] = s;
    } else if (t == 32) {
        float s = 0.f;
        for (int j = 0; j < HH; j++) s += be[j] * a[j];
        g_cb[l] = s;
    }
}

// ---------------- per-node alpha_src / alpha_dst ----------------
__global__ __launch_bounds__(256) void alpha_kernel(const float* __restrict__ gat_a, int l)
{
    int warp = threadIdx.x >> 5, lane = threadIdx.x & 31;
    int n = blockIdx.x * 8 + warp;
    const float* a = gat_a + l * (3 * HH);
    const float* mrow = g_m + (size_t)n * HH;
    float s = 0.f, d = 0.f;
#pragma unroll
    for (int j = lane; j < HH; j += 32) {
        float mv = mrow[j];
        s += mv * a[j];
        d += mv * a[HH + j];
    }
#pragma unroll
    for (int off = 16; off; off >>= 1) {
        s += __shfl_xor_sync(0xffffffffu, s, off);
        d += __shfl_xor_sync(0xffffffffu, d, off);
    }
    if (lane == 0) { g_as[n] = s; g_ad[n] = d; }
}

// ---------------- fused GAT node update ----------------
__global__ __launch_bounds__(256) void gat_update_kernel(
    const int* __restrict__ dst, const float* __restrict__ edge_feats,
    const float* __restrict__ lng, const float* __restrict__ lnb, int l)
{
    __shared__ float lg[DEG];
    __shared__ int   sd[DEG];
    __shared__ float rs[8], rs2[8];

    int n = blockIdx.x;
    int t = threadIdx.x;
    int warp = t >> 5, lane = t & 31;

    if (t < DEG) {
        int eid = n * DEG + t;
        int d = dst[eid];
        const float* ef = edge_feats + (size_t)eid * 32;
        const float* wa = g_wa + l * 32;
        float ce = g_cb[l];
#pragma unroll
        for (int j = 0; j < 32; j++) ce += ef[j] * wa[j];
        float x = g_as[n] + g_ad[d] + ce;
        lg[t] = (x >= 0.f) ? x : 0.01f * x;
        sd[t] = d;
    }
    __syncthreads();

    float mx = -1e30f;
#pragma unroll
    for (int k = 0; k < DEG; k++) mx = fmaxf(mx, lg[k]);
    float w[DEG]; float wsum = 0.f;
#pragma unroll
    for (int k = 0; k < DEG; k++) { w[k] = __expf(lg[k] - mx); wsum += w[k]; }
    float inv = 1.f / wsum;

    float acc = 0.f;
#pragma unroll
    for (int k = 0; k < DEG; k++) acc += (w[k] * inv) * g_m[(size_t)sd[k] * HH + t];

    float x = acc + g_h[(size_t)n * HH + t];

    float s = x, s2 = x * x;
#pragma unroll
    for (int off = 16; off; off >>= 1) {
        s  += __shfl_xor_sync(0xffffffffu, s,  off);
        s2 += __shfl_xor_sync(0xffffffffu, s2, off);
    }
    if (lane == 0) { rs[warp] = s; rs2[warp] = s2; }
    __syncthreads();
    if (warp == 0) {
        float a = (lane < 8) ? rs[lane]  : 0.f;
        float b = (lane < 8) ? rs2[lane] : 0.f;
#pragma unroll
        for (int off = 4; off; off >>= 1) {
            a += __shfl_xor_sync(0xffffffffu, a, off);
            b += __shfl_xor_sync(0xffffffffu, b, off);
        }
        if (lane == 0) { rs[0] = a; rs2[0] = b; }
    }
    __syncthreads();
    float mean = rs[0] * (1.f / HH);
    float var  = rs2[0] * (1.f / HH) - mean * mean;
    float y = (x - mean) * rsqrtf(var + 1e-5f) * lng[l * HH + t] + lnb[l * HH + t];
    size_t o = (size_t)n * HH + t;
    g_h[o] = y;
    __nv_bfloat16 hh = __float2bfloat16_rn(y);
    g_h_h[o] = hh;
    g_h_l[o] = __float2bfloat16_rn(y - __bfloat162float(hh));
}

// ---------------- residual + LayerNorm (+ optional bf16 hi/lo out) ----------------
__global__ __launch_bounds__(256) void ln_kernel(
    const float* __restrict__ xa, const float* __restrict__ xb,
    const float* __restrict__ g, const float* __restrict__ b,
    float* __restrict__ out,
    __nv_bfloat16* __restrict__ ohi, __nv_bfloat16* __restrict__ olo,
    float eps)
{
    __shared__ float rs[8], rs2[8];
    int n = blockIdx.x;
    int t = threadIdx.x;
    int warp = t >> 5, lane = t & 31;
    float x = xa[(size_t)n * HH + t] + xb[(size_t)n * HH + t];
    float s = x, s2 = x * x;
#pragma unroll
    for (int off = 16; off; off >>= 1) {
        s  += __shfl_xor_sync(0xffffffffu, s,  off);
        s2 += __shfl_xor_sync(0xffffffffu, s2, off);
    }
    if (lane == 0) { rs[warp] = s; rs2[warp] = s2; }
    __syncthreads();
    if (warp == 0) {
        float a = (lane < 8) ? rs[lane]  : 0.f;
        float c = (lane < 8) ? rs2[lane] : 0.f;
#pragma unroll
        for (int off = 4; off; off >>= 1) {
            a += __shfl_xor_sync(0xffffffffu, a, off);
            c += __shfl_xor_sync(0xffffffffu, c, off);
        }
        if (lane == 0) { rs[0] = a; rs2[0] = c; }
    }
    __syncthreads();
    float mean = rs[0] * (1.f / HH);
    float var  = rs2[0] * (1.f / HH) - mean * mean;
    float y = (x - mean) * rsqrtf(var + eps) * g[t] + b[t];
    size_t o = (size_t)n * HH + t;
    out[o] = y;
    if (ohi) {
        __nv_bfloat16 hh = __float2bfloat16_rn(y);
        ohi[o] = hh;
        olo[o] = __float2bfloat16_rn(y - __bfloat162float(hh));
    }
}

// ---------------- per-(graph, head) global attention (packed qkv) ----------------
__global__ __launch_bounds__(256) void attn_kernel()
{
    __shared__ float qs[NPG][33];
    __shared__ float ks[NPG][33];
    __shared__ float vs[NPG][DKH];
    __shared__ float pb[8][NPG];

    int head = blockIdx.x;
    int b = blockIdx.y;
    int t = threadIdx.x;
    int warp = t >> 5, lane = t & 31;

    for (int idx = t; idx < NPG * DKH; idx += 256) {
        int r = idx >> 5, d = idx & 31;
        size_t g = (size_t)(b * NPG + r) * 768 + head * DKH + d;
        qs[r][d] = g_qkv[g];
        ks[r][d] = g_qkv[g + 256];
        vs[r][d] = g_qkv[g + 512];
    }
    __syncthreads();

    const float scale = 0.17677669529663687f;
    for (int r = 0; r < 8; r++) {
        int i = warp * 8 + r;
        float s0 = 0.f, s1 = 0.f;
#pragma unroll
        for (int d = 0; d < DKH; d++) {
            float qd = qs[i][d];
            s0 += qd * ks[lane][d];
            s1 += qd * ks[lane + 32][d];
        }
        s0 *= scale; s1 *= scale;
        float mx = fmaxf(s0, s1);
#pragma unroll
        for (int off = 16; off; off >>= 1)
            mx = fmaxf(mx, __shfl_xor_sync(0xffffffffu, mx, off));
        float e0 = __expf(s0 - mx), e1 = __expf(s1 - mx);
        float sm = e0 + e1;
#pragma unroll
        for (int off = 16; off; off >>= 1)
            sm += __shfl_xor_sync(0xffffffffu, sm, off);
        float inv = 1.f / sm;
        pb[warp][lane] = e0 * inv;
        pb[warp][lane + 32] = e1 * inv;
        __syncwarp();
        float o = 0.f;
#pragma unroll
        for (int j = 0; j < NPG; j++) o += pb[warp][j] * vs[j][lane];
        g_o[(size_t)(b * NPG + i) * HH + head * DKH + lane] = o;
    }
}

// ---------------- gating scalar per node ----------------
__global__ __launch_bounds__(256) void gvec_kernel(const float* __restrict__ gW2,
                                                   const float* __restrict__ gb2)
{
    int warp = threadIdx.x >> 5, lane = threadIdx.x & 31;
    int n = blockIdx.x * 8 + warp;
    const float* row = g_m + (size_t)n * HH;
    float s = 0.f;
#pragma unroll
    for (int j = lane; j < HH; j += 32) s += row[j] * gW2[j];
#pragma unroll
    for (int off = 16; off; off >>= 1) s += __shfl_xor_sync(0xffffffffu, s, off);
    if (lane == 0) g_gs[n] = s + gb2[0];
}

// ---------------- gated readout per graph ----------------
__global__ __launch_bounds__(256) void readout_kernel(float* __restrict__ out)
{
    __shared__ float p[NPG];
    int b = blockIdx.x;
    int t = threadIdx.x;
    if (t < NPG) p[t] = g_gs[b * NPG + t];
    __syncthreads();
    float mx = -1e30f;
#pragma unroll
    for (int i = 0; i < NPG; i++) mx = fmaxf(mx, p[i]);
    float s = 0.f, acc = 0.f;
    for (int i = 0; i < NPG; i++) {
        float w = __expf(p[i] - mx);
        s += w;
        acc += w * g_h[(size_t)(b * NPG + i) * HH + t];
    }
    out[b * HH + t] = acc / s;
}

// ---------------- host launcher ----------------
static inline __nv_bfloat16* sym(const void* s)
{
    void* p = nullptr;
    cudaGetSymbolAddress(&p, s);
    return (__nv_bfloat16*)p;
}

extern "C" void kernel_launch(void* const* d_in, const int* in_sizes, int n_in,
                              void* d_out, int out_size)
{
    const float* node_feats = (const float*)d_in[0];
    const float* edge_feats = (const float*)d_in[1];
    const int*   dst        = (const int*)  d_in[3];
    const float* Wn   = (const float*)d_in[4];
    const float* bn   = (const float*)d_in[5];
    const float* We   = (const float*)d_in[6];
    const float* be   = (const float*)d_in[7];
    const float* gatW = (const float*)d_in[8];
    const float* gata = (const float*)d_in[9];
    const float* glng = (const float*)d_in[10];
    const float* glnb = (const float*)d_in[11];
    const float* Wq   = (const float*)d_in[12];
    const float* Wk   = (const float*)d_in[13];
    const float* Wv   = (const float*)d_in[14];
    const float* alng = (const float*)d_in[15];
    const float* alnb = (const float*)d_in[16];
    const float* fW1  = (const float*)d_in[17];
    const float* fb1  = (const float*)d_in[18];
    const float* fW2  = (const float*)d_in[19];
    const float* fb2  = (const float*)d_in[20];
    const float* flng = (const float*)d_in[21];
    const float* flnb = (const float*)d_in[22];
    const float* gW1  = (const float*)d_in[23];
    const float* gb1  = (const float*)d_in[24];
    const float* gW2  = (const float*)d_in[25];
    const float* gb2  = (const float*)d_in[26];
    float* out = (float*)d_out;

    cudaFuncSetAttribute(gemm_tc, cudaFuncAttributeMaxDynamicSharedMemorySize,
                         SMEM_GEMM);

    float *h_p, *m_p, *qkv_p, *o_p;
    cudaGetSymbolAddress((void**)&h_p, g_h);
    cudaGetSymbolAddress((void**)&m_p, g_m);
    cudaGetSymbolAddress((void**)&qkv_p, g_qkv);
    cudaGetSymbolAddress((void**)&o_p, g_o);

    __nv_bfloat16 *nf_h = sym(g_nf_h), *nf_l = sym(g_nf_l);
    __nv_bfloat16 *h_h = sym(g_h_h),  *h_l = sym(g_h_l);
    __nv_bfloat16 *ff_h = sym(g_ff_h), *ff_l = sym(g_ff_l);
    __nv_bfloat16 *wnt_h = sym(g_wnt_h), *wnt_l = sym(g_wnt_l);
    __nv_bfloat16 *gwt_h = sym(g_gatwt_h), *gwt_l = sym(g_gatwt_l);
    __nv_bfloat16 *qkvt_h = sym(g_qkvt_h), *qkvt_l = sym(g_qkvt_l);
    __nv_bfloat16 *f1t_h = sym(g_ff1t_h), *f1t_l = sym(g_ff1t_l);
    __nv_bfloat16 *f2t_h = sym(g_ff2t_h), *f2t_l = sym(g_ff2t_l);
    __nv_bfloat16 *g1t_h = sym(g_gw1t_h), *g1t_l = sym(g_gw1t_l);

    ConvTab tab;
    int ne = 0, blk = 0;
    auto add = [&](const float* s, __nv_bfloat16* hi, __nv_bfloat16* lo,
                   int K, int N, int tr) {
        int nb = (K * N + 1023) / 1024;
        tab.e[ne] = {s, hi, lo, K, N, tr, blk, nb};
        blk += nb; ne++;
    };
    add(Wn, wnt_h, wnt_l, 64, HH, 1);
    for (int l = 0; l < LL; l++)
        add(gatW + (size_t)l * HH * HH, gwt_h + (size_t)l * HH * HH,
            gwt_l + (size_t)l * HH * HH, HH, HH, 1);
    add(Wq, qkvt_h, qkvt_l, HH, HH, 1);
    add(Wk, qkvt_h + 256 * HH, qkvt_l + 256 * HH, HH, HH, 1);
    add(Wv, qkvt_h + 512 * HH, qkvt_l + 512 * HH, HH, HH, 1);
    add(fW1, f1t_h, f1t_l, HH, FFD, 1);
    add(fW2, f2t_h, f2t_l, FFD, HH, 1);
    add(gW1, g1t_h, g1t_l, HH, HH, 1);
    add(node_feats, nf_h, nf_l, NN, 64, 0);
    tab.n = ne;

    conv_kernel<<<blk, 256>>>(tab);
    wa_kernel<<<LL, 64>>>(We, be, gata);

    dim3 gH(HH / 128, NN / 128);     // (2, 128)
    dim3 gQKV(768 / 128, NN / 128);  // (6, 128)
    dim3 gF(FFD / 128, NN / 128);    // (4, 128)

    gemm_tc<<<gH, 256, SMEM_GEMM>>>(nf_h, nf_l, wnt_h, wnt_l, bn, h_p, h_h, h_l,
                                    NN, 64, HH, 0);

    for (int l = 0; l < LL; l++) {
        gemm_tc<<<gH, 256, SMEM_GEMM>>>(h_h, h_l, gwt_h + (size_t)l * HH * HH,
                                        gwt_l + (size_t)l * HH * HH, nullptr,
                                        m_p, nullptr, nullptr, NN, HH, HH, 0);
        alpha_kernel<<<NN / 8, 256>>>(gata, l);
        gat_update_kernel<<<NN, 256>>>(dst, edge_feats, glng, glnb, l);
    }

    // fused QKV projection
    gemm_tc<<<gQKV, 256, SMEM_GEMM>>>(h_h, h_l, qkvt_h, qkvt_l, nullptr, qkv_p,
                                      nullptr, nullptr, NN, HH, 768, 0);
    attn_kernel<<<dim3(NHEADS, GB), 256>>>();
    ln_kernel<<<NN, 256>>>(o_p, h_p, alng, alnb, h_p, h_h, h_l, 1e-6f);

    // feed-forward
    gemm_tc<<<gF, 256, SMEM_GEMM>>>(h_h, h_l, f1t_h, f1t_l, fb1, nullptr,
                                    ff_h, ff_l, NN, HH, FFD, 2);
    gemm_tc<<<gH, 256, SMEM_GEMM>>>(ff_h, ff_l, f2t_h, f2t_l, fb2, m_p,
                                    nullptr, nullptr, NN, FFD, HH, 0);
    ln_kernel<<<NN, 256>>>(h_p, m_p, flng, flnb, h_p, h_h, h_l, 1e-6f);

    // gating readout
    gemm_tc<<<gH, 256, SMEM_GEMM>>>(h_h, h_l, g1t_h, g1t_l, gb1, m_p,
                                    nullptr, nullptr, NN, HH, HH, 1);
    gvec_kernel<<<NN / 8, 256>>>(gW2, gb2);
    readout_kernel<<<GB, 256>>>(out);

    (void)in_sizes; (void)n_in; (void)out_size;
}

// round 5
// speedup vs baseline: 2.1958x; 1.1774x over previous
#include <cuda_runtime.h>
#include <cuda_bf16.h>
#include <math.h>
#include <stdint.h>

// ---------------- problem constants ----------------
#define NN      16384
#define EE      131072
#define HH      256
#define LL      4
#define GB      256
#define NPG     64
#define NHEADS  8
#define DKH     32
#define DEG     8
#define FFD     512

// ---------------- fp32 scratch ----------------
__device__ float g_h[NN * HH];
__device__ float g_m[NN * HH];
__device__ float g_qkv[NN * 768];
__device__ float g_o[NN * HH];
__device__ float g_gs[NN];
__device__ float g_wa[LL * 32];
__device__ float g_cb[LL];
__device__ float g_ce[LL * EE];

// ---------------- bf16 hi/lo scratch (activations) ----------------
__device__ __nv_bfloat16 g_nf_h[NN * 64],   g_nf_l[NN * 64];
__device__ __nv_bfloat16 g_h_h[NN * HH],    g_h_l[NN * HH];
__device__ __nv_bfloat16 g_ff_h[NN * FFD],  g_ff_l[NN * FFD];

// ---------------- bf16 hi/lo weights, transposed to [N][K] ----------------
__device__ __nv_bfloat16 g_wnt_h[HH * 64],        g_wnt_l[HH * 64];
__device__ __nv_bfloat16 g_gatwt_h[LL * HH * HH], g_gatwt_l[LL * HH * HH];
__device__ __nv_bfloat16 g_qkvt_h[768 * HH], g_qkvt_l[768 * HH];
__device__ __nv_bfloat16 g_ff1t_h[FFD * HH], g_ff1t_l[FFD * HH];
__device__ __nv_bfloat16 g_ff2t_h[HH * FFD], g_ff2t_l[HH * FFD];
__device__ __nv_bfloat16 g_gw1t_h[HH * HH],  g_gw1t_l[HH * HH];

// ================= conversion: fp32 -> (bf16 hi, lo), optional transpose =========
struct ConvEnt {
    const float* src;
    __nv_bfloat16* hi;
    __nv_bfloat16* lo;
    int K, N, trans, blk0, nblk;
};
struct ConvTab { ConvEnt e[13]; int n; };

__global__ __launch_bounds__(256) void conv_kernel(ConvTab tab)
{
    int b = blockIdx.x;
    int ei = 0;
    for (int i = 0; i < tab.n; i++)
        if (b >= tab.e[i].blk0) ei = i;
    ConvEnt e = tab.e[ei];
    int lb = b - e.blk0;
    int total = e.K * e.N;
    int base = lb * 1024;
#pragma unroll
    for (int j = 0; j < 4; j++) {
        int i = base + j * 256 + threadIdx.x;
        if (i < total) {
            float x = e.src[i];
            __nv_bfloat16 h = __float2bfloat16_rn(x);
            __nv_bfloat16 l = __float2bfloat16_rn(x - __bfloat162float(h));
            int di;
            if (e.trans) { int k = i / e.N, n = i % e.N; di = n * e.K + k; }
            else di = i;
            e.hi[di] = h;
            e.lo[di] = l;
        }
    }
}

// ================= pipelined tensor-core GEMM (ldmatrix, BK=32) ==========
#define SA   40
#define BUFE (128 * SA)
#define SMEM_GEMM (8 * BUFE * 2)

__device__ __forceinline__ void mma_bf16(float* c, const uint32_t* a,
                                         uint32_t b0, uint32_t b1)
{
    asm volatile(
        "mma.sync.aligned.m16n8k16.row.col.f32.bf16.bf16.f32 "
        "{%0,%1,%2,%3}, {%4,%5,%6,%7}, {%8,%9}, {%0,%1,%2,%3};\n"
        : "+f"(c[0]), "+f"(c[1]), "+f"(c[2]), "+f"(c[3])
        : "r"(a[0]), "r"(a[1]), "r"(a[2]), "r"(a[3]), "r"(b0), "r"(b1));
}

__device__ __forceinline__ void cp16(void* s, const void* g)
{
    uint32_t sa = (uint32_t)__cvta_generic_to_shared(s);
    asm volatile("cp.async.ca.shared.global [%0], [%1], 16;\n" :: "r"(sa), "l"(g));
}

__device__ __forceinline__ void ldmat4(uint32_t& r0, uint32_t& r1,
                                       uint32_t& r2, uint32_t& r3, uint32_t addr)
{
    asm volatile("ldmatrix.sync.aligned.m8n8.x4.shared.b16 {%0,%1,%2,%3}, [%4];\n"
                 : "=r"(r0), "=r"(r1), "=r"(r2), "=r"(r3) : "r"(addr));
}

__global__ __launch_bounds__(256, 2) void gemm_tc(
    const __nv_bfloat16* __restrict__ Ah, const __nv_bfloat16* __restrict__ Al,
    const __nv_bfloat16* __restrict__ Bh, const __nv_bfloat16* __restrict__ Bl,
    const float* __restrict__ bias,
    float* __restrict__ Cf,
    __nv_bfloat16* __restrict__ Chi, __nv_bfloat16* __restrict__ Clo,
    int M, int K, int Nout, int act)
{
    extern __shared__ __nv_bfloat16 sm[];
    __nv_bfloat16* sAh = sm;
    __nv_bfloat16* sAl = sm + 2 * BUFE;
    __nv_bfloat16* sBh = sm + 4 * BUFE;
    __nv_bfloat16* sBl = sm + 6 * BUFE;

    const int t = threadIdx.x;
    const int warp = t >> 5, lane = t & 31;
    const int wm = (warp & 1) * 64;
    const int wn = (warp >> 1) * 32;
    const int r = lane >> 2, c2 = (lane & 3) * 2;
    const int m0 = blockIdx.y * 128;
    const int n0 = blockIdx.x * 128;

    const int lr = t >> 2;
    const int lc = (t & 3) * 8;

    const int g8 = lane >> 3;
    const int lrow = (g8 & 1) * 8 + (lane & 7);
    const int kof = (g8 >> 1) * 8;

    float acc[4][4][4];
#pragma unroll
    for (int i = 0; i < 4; i++)
#pragma unroll
        for (int j = 0; j < 4; j++)
#pragma unroll
            for (int k = 0; k < 4; k++) acc[i][j][k] = 0.f;

    const __nv_bfloat16* pAh = Ah + (size_t)(m0 + lr) * K + lc;
    const __nv_bfloat16* pAl = Al + (size_t)(m0 + lr) * K + lc;
    const __nv_bfloat16* pBh = Bh + (size_t)(n0 + lr) * K + lc;
    const __nv_bfloat16* pBl = Bl + (size_t)(n0 + lr) * K + lc;
    const size_t rs64 = (size_t)64 * K;

    const int so0 = lr * SA + lc;
    const int so1 = (lr + 64) * SA + lc;

    uint32_t bAh = (uint32_t)__cvta_generic_to_shared(sAh);
    uint32_t bAl = (uint32_t)__cvta_generic_to_shared(sAl);
    uint32_t bBh = (uint32_t)__cvta_generic_to_shared(sBh);
    uint32_t bBl = (uint32_t)__cvta_generic_to_shared(sBl);

    // precomputed ldmatrix byte offsets (stage/ks added in loop)
    uint32_t aoff[4], boff[2];
#pragma unroll
    for (int mt = 0; mt < 4; mt++)
        aoff[mt] = ((wm + mt * 16 + lrow) * SA + kof) * 2;
#pragma unroll
    for (int ntp = 0; ntp < 2; ntp++)
        boff[ntp] = ((wn + ntp * 16 + lrow) * SA + kof) * 2;

    cp16(&sAh[so0], pAh);            cp16(&sAh[so1], pAh + rs64);
    cp16(&sAl[so0], pAl);            cp16(&sAl[so1], pAl + rs64);
    cp16(&sBh[so0], pBh);            cp16(&sBh[so1], pBh + rs64);
    cp16(&sBl[so0], pBl);            cp16(&sBl[so1], pBl + rs64);
    asm volatile("cp.async.commit_group;\n");

    const int nIter = K >> 5;
    for (int i = 0; i < nIter; i++) {
        const int s = i & 1;
        if (i + 1 < nIter) {
            int k0 = (i + 1) << 5;
            int nso = ((i + 1) & 1) * BUFE;
            cp16(&sAh[nso + so0], pAh + k0);  cp16(&sAh[nso + so1], pAh + rs64 + k0);
            cp16(&sAl[nso + so0], pAl + k0);  cp16(&sAl[nso + so1], pAl + rs64 + k0);
            cp16(&sBh[nso + so0], pBh + k0);  cp16(&sBh[nso + so1], pBh + rs64 + k0);
            cp16(&sBl[nso + so0], pBl + k0);  cp16(&sBl[nso + so1], pBl + rs64 + k0);
            asm volatile("cp.async.commit_group;\n");
            asm volatile("cp.async.wait_group 1;\n");
        } else {
            asm volatile("cp.async.wait_group 0;\n");
        }
        __syncthreads();

        const uint32_t sb = s * BUFE * 2;
#pragma unroll
        for (int ks = 0; ks < 2; ks++) {
            const uint32_t kso = sb + ks * 32;
            uint32_t ah[4][4], al[4][4];
#pragma unroll
            for (int mt = 0; mt < 4; mt++) {
                ldmat4(ah[mt][0], ah[mt][1], ah[mt][2], ah[mt][3], bAh + kso + aoff[mt]);
                ldmat4(al[mt][0], al[mt][1], al[mt][2], al[mt][3], bAl + kso + aoff[mt]);
            }
#pragma unroll
            for (int ntp = 0; ntp < 2; ntp++) {
                uint32_t h0, h1, h2, h3, l0, l1, l2, l3;
                ldmat4(h0, h1, h2, h3, bBh + kso + boff[ntp]);
                ldmat4(l0, l1, l2, l3, bBl + kso + boff[ntp]);
#pragma unroll
                for (int mt = 0; mt < 4; mt++) {
                    mma_bf16(acc[mt][2 * ntp],     ah[mt], h0, h2);
                    mma_bf16(acc[mt][2 * ntp],     al[mt], h0, h2);
                    mma_bf16(acc[mt][2 * ntp],     ah[mt], l0, l2);
                    mma_bf16(acc[mt][2 * ntp + 1], ah[mt], h1, h3);
                    mma_bf16(acc[mt][2 * ntp + 1], al[mt], h1, h3);
                    mma_bf16(acc[mt][2 * ntp + 1], ah[mt], l1, l3);
                }
            }
        }
        __syncthreads();
    }

#pragma unroll
    for (int nt = 0; nt < 4; nt++) {
        int col = n0 + wn + nt * 8 + c2;
        float b0 = bias ? bias[col] : 0.f;
        float b1 = bias ? bias[col + 1] : 0.f;
#pragma unroll
        for (int mt = 0; mt < 4; mt++) {
            int row = m0 + wm + mt * 16 + r;
#pragma unroll
            for (int half = 0; half < 2; half++) {
                int rr = row + half * 8;
                float v0 = acc[mt][nt][half * 2 + 0] + b0;
                float v1 = acc[mt][nt][half * 2 + 1] + b1;
                if (act == 1) { v0 = fmaxf(v0, 0.f); v1 = fmaxf(v1, 0.f); }
                else if (act == 2) {
                    v0 = 0.5f * v0 * (1.f + erff(v0 * 0.70710678118654752f));
                    v1 = 0.5f * v1 * (1.f + erff(v1 * 0.70710678118654752f));
                }
                size_t o = (size_t)rr * Nout + col;
                if (Cf) *(float2*)(Cf + o) = make_float2(v0, v1);
                if (Chi) {
                    __nv_bfloat16 h0 = __float2bfloat16_rn(v0);
                    __nv_bfloat16 h1 = __float2bfloat16_rn(v1);
                    __nv_bfloat162 hp; hp.x = h0; hp.y = h1;
                    *(__nv_bfloat162*)(Chi + o) = hp;
                    __nv_bfloat162 lp;
                    lp.x = __float2bfloat16_rn(v0 - __bfloat162float(h0));
                    lp.y = __float2bfloat16_rn(v1 - __bfloat162float(h1));
                    *(__nv_bfloat162*)(Clo + o) = lp;
                }
            }
        }
    }
}

// ---------------- fold edge projection into per-layer 32-dim vector ----------------
__global__ void wa_kernel(const float* __restrict__ We, const float* __restrict__ be,
                          const float* __restrict__ gat_a)
{
    int l = blockIdx.x;
    int t = threadIdx.x;
    const float* a = gat_a + l * (3 * HH) + 2 * HH;
    if (t < 32) {
        float s = 0.f;
        const float* row = We + t * HH;
        for (int j = 0; j < HH; j++) s += row[j] * a[j];
        g_wa[l * 32 + t] = s;
    } else if (t == 32) {
        float s = 0.f;
        for (int j = 0; j < HH; j++) s += be[j] * a[j];
        g_cb[l] = s;
    }
}

// ---------------- per-edge ce for ALL layers (edge_feats read once) ----------------
__global__ __launch_bounds__(256) void ce_kernel(const float* __restrict__ ef)
{
    int e = blockIdx.x * 256 + threadIdx.x;
    float4 v[8];
    const float4* row = (const float4*)(ef + (size_t)e * 32);
#pragma unroll
    for (int i = 0; i < 8; i++) v[i] = row[i];
#pragma unroll
    for (int l = 0; l < LL; l++) {
        const float* wa = g_wa + l * 32;
        float s = g_cb[l];
#pragma unroll
        for (int i = 0; i < 8; i++) {
            s += v[i].x * wa[4 * i + 0];
            s += v[i].y * wa[4 * i + 1];
            s += v[i].z * wa[4 * i + 2];
            s += v[i].w * wa[4 * i + 3];
        }
        g_ce[l * EE + e] = s;
    }
}

// ---------------- graph-resident GAT layer ----------------
// 1 block = 1 graph (64 nodes). Fuses alpha dots, edge logits, softmax(8),
// aggregation from smem-resident m tile, residual + LN, bf16 hi/lo split.
#define GATSM (NPG * HH * 4 + (64 + 64 + 512) * 4 + 512 * 4)

__global__ __launch_bounds__(256) void gat_layer_kernel(
    const int* __restrict__ dst, const float* __restrict__ ce_l,
    const float* __restrict__ gat_a,
    const float* __restrict__ lng, const float* __restrict__ lnb, int l)
{
    extern __shared__ float smf[];
    float* smm = smf;                       // [64][256]
    float* sas = smf + NPG * HH;            // 64
    float* sad = sas + 64;                  // 64
    float* swt = sad + 64;                  // 512
    int*   sdl = (int*)(swt + 512);         // 512

    const int g = blockIdx.x;
    const int t = threadIdx.x;
    const int warp = t >> 5, lane = t & 31;

    // 1) load the graph's m tile (contiguous 64 KB)
    {
        const float4* src = (const float4*)(g_m + (size_t)g * NPG * HH);
        float4* dstp = (float4*)smm;
#pragma unroll
        for (int i = 0; i < 16; i++)
            dstp[t + 256 * i] = src[t + 256 * i];
    }
    __syncthreads();

    // 2) alpha dots per node (warp handles 8 nodes)
    {
        const float* a1 = gat_a + l * (3 * HH);
        const float* a2 = a1 + HH;
#pragma unroll
        for (int q = 0; q < 8; q++) {
            int i = warp * 8 + q;
            const float* mr = smm + i * HH;
            float s = 0.f, d = 0.f;
#pragma unroll
            for (int j = lane; j < HH; j += 32) {
                float mv = mr[j];
                s += mv * a1[j];
                d += mv * a2[j];
            }
#pragma unroll
            for (int off = 16; off; off >>= 1) {
                s += __shfl_xor_sync(0xffffffffu, s, off);
                d += __shfl_xor_sync(0xffffffffu, d, off);
            }
            if (lane == 0) { sas[i] = s; sad[i] = d; }
        }
    }
    __syncthreads();

    // 3) logits + local softmax (thread per node, t<64)
    if (t < NPG) {
        float lg[DEG];
        int   dl[DEG];
#pragma unroll
        for (int k = 0; k < DEG; k++) {
            int e = t * DEG + k;
            int d = dst[g * (NPG * DEG) + e] - g * NPG;
            dl[k] = d;
            float x = sas[t] + sad[d] + ce_l[g * (NPG * DEG) + e];
            lg[k] = (x >= 0.f) ? x : 0.01f * x;
        }
        float mx = -1e30f;
#pragma unroll
        for (int k = 0; k < DEG; k++) mx = fmaxf(mx, lg[k]);
        float ws = 0.f;
#pragma unroll
        for (int k = 0; k < DEG; k++) { lg[k] = __expf(lg[k] - mx); ws += lg[k]; }
        float inv = 1.f / ws;
#pragma unroll
        for (int k = 0; k < DEG; k++) {
            swt[t * DEG + k] = lg[k] * inv;
            sdl[t * DEG + k] = dl[k];
        }
    }
    __syncthreads();

    // 4) aggregation + residual + LN + write (warp per node, 8 nodes/warp)
#pragma unroll
    for (int q = 0; q < 8; q++) {
        int i = warp * 8 + q;
        float acc[8] = {0.f, 0.f, 0.f, 0.f, 0.f, 0.f, 0.f, 0.f};
#pragma unroll
        for (int k = 0; k < DEG; k++) {
            float wk = swt[i * DEG + k];
            const float4* mr = (const float4*)(smm + sdl[i * DEG + k] * HH) + lane * 2;
            float4 v0 = mr[0], v1 = mr[1];
            acc[0] += wk * v0.x; acc[1] += wk * v0.y;
            acc[2] += wk * v0.z; acc[3] += wk * v0.w;
            acc[4] += wk * v1.x; acc[5] += wk * v1.y;
            acc[6] += wk * v1.z; acc[7] += wk * v1.w;
        }
        size_t rowo = (size_t)(g * NPG + i) * HH + lane * 8;
        const float4* hr = (const float4*)(g_h + rowo);
        float4 h0 = hr[0], h1 = hr[1];
        float x[8];
        x[0] = acc[0] + h0.x; x[1] = acc[1] + h0.y;
        x[2] = acc[2] + h0.z; x[3] = acc[3] + h0.w;
        x[4] = acc[4] + h1.x; x[5] = acc[5] + h1.y;
        x[6] = acc[6] + h1.z; x[7] = acc[7] + h1.w;

        float s = 0.f, s2 = 0.f;
#pragma unroll
        for (int c = 0; c < 8; c++) { s += x[c]; s2 += x[c] * x[c]; }
#pragma unroll
        for (int off = 16; off; off >>= 1) {
            s  += __shfl_xor_sync(0xffffffffu, s,  off);
            s2 += __shfl_xor_sync(0xffffffffu, s2, off);
        }
        float mean = s * (1.f / HH);
        float var  = s2 * (1.f / HH) - mean * mean;
        float rstd = rsqrtf(var + 1e-5f);

        const float4* gg = (const float4*)(lng + l * HH + lane * 8);
        const float4* bb = (const float4*)(lnb + l * HH + lane * 8);
        float4 gv0 = gg[0], gv1 = gg[1];
        float4 bv0 = bb[0], bv1 = bb[1];
        float y[8];
        y[0] = (x[0] - mean) * rstd * gv0.x + bv0.x;
        y[1] = (x[1] - mean) * rstd * gv0.y + bv0.y;
        y[2] = (x[2] - mean) * rstd * gv0.z + bv0.z;
        y[3] = (x[3] - mean) * rstd * gv0.w + bv0.w;
        y[4] = (x[4] - mean) * rstd * gv1.x + bv1.x;
        y[5] = (x[5] - mean) * rstd * gv1.y + bv1.y;
        y[6] = (x[6] - mean) * rstd * gv1.z + bv1.z;
        y[7] = (x[7] - mean) * rstd * gv1.w + bv1.w;

        float4* ho = (float4*)(g_h + rowo);
        ho[0] = make_float4(y[0], y[1], y[2], y[3]);
        ho[1] = make_float4(y[4], y[5], y[6], y[7]);

        uint32_t hi[4], lo[4];
#pragma unroll
        for (int c = 0; c < 4; c++) {
            __nv_bfloat16 a0 = __float2bfloat16_rn(y[2 * c]);
            __nv_bfloat16 a1 = __float2bfloat16_rn(y[2 * c + 1]);
            __nv_bfloat162 hp; hp.x = a0; hp.y = a1;
            hi[c] = *(uint32_t*)&hp;
            __nv_bfloat162 lp;
            lp.x = __float2bfloat16_rn(y[2 * c] - __bfloat162float(a0));
            lp.y = __float2bfloat16_rn(y[2 * c + 1] - __bfloat162float(a1));
            lo[c] = *(uint32_t*)&lp;
        }
        *(uint4*)(g_h_h + rowo) = make_uint4(hi[0], hi[1], hi[2], hi[3]);
        *(uint4*)(g_h_l + rowo) = make_uint4(lo[0], lo[1], lo[2], lo[3]);
    }
}

// ---------------- residual + LayerNorm (+ optional bf16 hi/lo out) ----------------
__global__ __launch_bounds__(256) void ln_kernel(
    const float* __restrict__ xa, const float* __restrict__ xb,
    const float* __restrict__ g, const float* __restrict__ b,
    float* __restrict__ out,
    __nv_bfloat16* __restrict__ ohi, __nv_bfloat16* __restrict__ olo,
    float eps)
{
    __shared__ float rs[8], rs2[8];
    int n = blockIdx.x;
    int t = threadIdx.x;
    int warp = t >> 5, lane = t & 31;
    float x = xa[(size_t)n * HH + t] + xb[(size_t)n * HH + t];
    float s = x, s2 = x * x;
#pragma unroll
    for (int off = 16; off; off >>= 1) {
        s  += __shfl_xor_sync(0xffffffffu, s,  off);
        s2 += __shfl_xor_sync(0xffffffffu, s2, off);
    }
    if (lane == 0) { rs[warp] = s; rs2[warp] = s2; }
    __syncthreads();
    if (warp == 0) {
        float a = (lane < 8) ? rs[lane]  : 0.f;
        float c = (lane < 8) ? rs2[lane] : 0.f;
#pragma unroll
        for (int off = 4; off; off >>= 1) {
            a += __shfl_xor_sync(0xffffffffu, a, off);
            c += __shfl_xor_sync(0xffffffffu, c, off);
        }
        if (lane == 0) { rs[0] = a; rs2[0] = c; }
    }
    __syncthreads();
    float mean = rs[0] * (1.f / HH);
    float var  = rs2[0] * (1.f / HH) - mean * mean;
    float y = (x - mean) * rsqrtf(var + eps) * g[t] + b[t];
    size_t o = (size_t)n * HH + t;
    out[o] = y;
    if (ohi) {
        __nv_bfloat16 hh = __float2bfloat16_rn(y);
        ohi[o] = hh;
        olo[o] = __float2bfloat16_rn(y - __bfloat162float(hh));
    }
}

// ---------------- per-(graph, head) global attention (packed qkv) ----------------
__global__ __launch_bounds__(256) void attn_kernel()
{
    __shared__ float qs[NPG][33];
    __shared__ float ks[NPG][33];
    __shared__ float vs[NPG][DKH];
    __shared__ float pb[8][NPG];

    int head = blockIdx.x;
    int b = blockIdx.y;
    int t = threadIdx.x;
    int warp = t >> 5, lane = t & 31;

    for (int idx = t; idx < NPG * DKH; idx += 256) {
        int r = idx >> 5, d = idx & 31;
        size_t g = (size_t)(b * NPG + r) * 768 + head * DKH + d;
        qs[r][d] = g_qkv[g];
        ks[r][d] = g_qkv[g + 256];
        vs[r][d] = g_qkv[g + 512];
    }
    __syncthreads();

    const float scale = 0.17677669529663687f;
    for (int r = 0; r < 8; r++) {
        int i = warp * 8 + r;
        float s0 = 0.f, s1 = 0.f;
#pragma unroll
        for (int d = 0; d < DKH; d++) {
            float qd = qs[i][d];
            s0 += qd * ks[lane][d];
            s1 += qd * ks[lane + 32][d];
        }
        s0 *= scale; s1 *= scale;
        float mx = fmaxf(s0, s1);
#pragma unroll
        for (int off = 16; off; off >>= 1)
            mx = fmaxf(mx, __shfl_xor_sync(0xffffffffu, mx, off));
        float e0 = __expf(s0 - mx), e1 = __expf(s1 - mx);
        float sm = e0 + e1;
#pragma unroll
        for (int off = 16; off; off >>= 1)
            sm += __shfl_xor_sync(0xffffffffu, sm, off);
        float inv = 1.f / sm;
        pb[warp][lane] = e0 * inv;
        pb[warp][lane + 32] = e1 * inv;
        __syncwarp();
        float o = 0.f;
#pragma unroll
        for (int j = 0; j < NPG; j++) o += pb[warp][j] * vs[j][lane];
        g_o[(size_t)(b * NPG + i) * HH + head * DKH + lane] = o;
    }
}

// ---------------- gating scalar per node ----------------
__global__ __launch_bounds__(256) void gvec_kernel(const float* __restrict__ gW2,
                                                   const float* __restrict__ gb2)
{
    int warp = threadIdx.x >> 5, lane = threadIdx.x & 31;
    int n = blockIdx.x * 8 + warp;
    const float* row = g_m + (size_t)n * HH;
    float s = 0.f;
#pragma unroll
    for (int j = lane; j < HH; j += 32) s += row[j] * gW2[j];
#pragma unroll
    for (int off = 16; off; off >>= 1) s += __shfl_xor_sync(0xffffffffu, s, off);
    if (lane == 0) g_gs[n] = s + gb2[0];
}

// ---------------- gated readout per graph ----------------
__global__ __launch_bounds__(256) void readout_kernel(float* __restrict__ out)
{
    __shared__ float p[NPG];
    int b = blockIdx.x;
    int t = threadIdx.x;
    if (t < NPG) p[t] = g_gs[b * NPG + t];
    __syncthreads();
    float mx = -1e30f;
#pragma unroll
    for (int i = 0; i < NPG; i++) mx = fmaxf(mx, p[i]);
    float s = 0.f, acc = 0.f;
    for (int i = 0; i < NPG; i++) {
        float w = __expf(p[i] - mx);
        s += w;
        acc += w * g_h[(size_t)(b * NPG + i) * HH + t];
    }
    out[b * HH + t] = acc / s;
}

// ---------------- host launcher ----------------
static inline __nv_bfloat16* sym(const void* s)
{
    void* p = nullptr;
    cudaGetSymbolAddress(&p, s);
    return (__nv_bfloat16*)p;
}

extern "C" void kernel_launch(void* const* d_in, const int* in_sizes, int n_in,
                              void* d_out, int out_size)
{
    const float* node_feats = (const float*)d_in[0];
    const float* edge_feats = (const float*)d_in[1];
    const int*   dst        = (const int*)  d_in[3];
    const float* Wn   = (const float*)d_in[4];
    const float* bn   = (const float*)d_in[5];
    const float* We   = (const float*)d_in[6];
    const float* be   = (const float*)d_in[7];
    const float* gatW = (const float*)d_in[8];
    const float* gata = (const float*)d_in[9];
    const float* glng = (const float*)d_in[10];
    const float* glnb = (const float*)d_in[11];
    const float* Wq   = (const float*)d_in[12];
    const float* Wk   = (const float*)d_in[13];
    const float* Wv   = (const float*)d_in[14];
    const float* alng = (const float*)d_in[15];
    const float* alnb = (const float*)d_in[16];
    const float* fW1  = (const float*)d_in[17];
    const float* fb1  = (const float*)d_in[18];
    const float* fW2  = (const float*)d_in[19];
    const float* fb2  = (const float*)d_in[20];
    const float* flng = (const float*)d_in[21];
    const float* flnb = (const float*)d_in[22];
    const float* gW1  = (const float*)d_in[23];
    const float* gb1  = (const float*)d_in[24];
    const float* gW2  = (const float*)d_in[25];
    const float* gb2  = (const float*)d_in[26];
    float* out = (float*)d_out;

    cudaFuncSetAttribute(gemm_tc, cudaFuncAttributeMaxDynamicSharedMemorySize,
                         SMEM_GEMM);
    cudaFuncSetAttribute(gat_layer_kernel,
                         cudaFuncAttributeMaxDynamicSharedMemorySize, GATSM);

    float *h_p, *m_p, *qkv_p, *o_p, *ce_p;
    cudaGetSymbolAddress((void**)&h_p, g_h);
    cudaGetSymbolAddress((void**)&m_p, g_m);
    cudaGetSymbolAddress((void**)&qkv_p, g_qkv);
    cudaGetSymbolAddress((void**)&o_p, g_o);
    cudaGetSymbolAddress((void**)&ce_p, g_ce);

    __nv_bfloat16 *nf_h = sym(g_nf_h), *nf_l = sym(g_nf_l);
    __nv_bfloat16 *h_h = sym(g_h_h),  *h_l = sym(g_h_l);
    __nv_bfloat16 *ff_h = sym(g_ff_h), *ff_l = sym(g_ff_l);
    __nv_bfloat16 *wnt_h = sym(g_wnt_h), *wnt_l = sym(g_wnt_l);
    __nv_bfloat16 *gwt_h = sym(g_gatwt_h), *gwt_l = sym(g_gatwt_l);
    __nv_bfloat16 *qkvt_h = sym(g_qkvt_h), *qkvt_l = sym(g_qkvt_l);
    __nv_bfloat16 *f1t_h = sym(g_ff1t_h), *f1t_l = sym(g_ff1t_l);
    __nv_bfloat16 *f2t_h = sym(g_ff2t_h), *f2t_l = sym(g_ff2t_l);
    __nv_bfloat16 *g1t_h = sym(g_gw1t_h), *g1t_l = sym(g_gw1t_l);

    ConvTab tab;
    int ne = 0, blk = 0;
    auto add = [&](const float* s, __nv_bfloat16* hi, __nv_bfloat16* lo,
                   int K, int N, int tr) {
        int nb = (K * N + 1023) / 1024;
        tab.e[ne] = {s, hi, lo, K, N, tr, blk, nb};
        blk += nb; ne++;
    };
    add(Wn, wnt_h, wnt_l, 64, HH, 1);
    for (int l = 0; l < LL; l++)
        add(gatW + (size_t)l * HH * HH, gwt_h + (size_t)l * HH * HH,
            gwt_l + (size_t)l * HH * HH, HH, HH, 1);
    add(Wq, qkvt_h, qkvt_l, HH, HH, 1);
    add(Wk, qkvt_h + 256 * HH, qkvt_l + 256 * HH, HH, HH, 1);
    add(Wv, qkvt_h + 512 * HH, qkvt_l + 512 * HH, HH, HH, 1);
    add(fW1, f1t_h, f1t_l, HH, FFD, 1);
    add(fW2, f2t_h, f2t_l, FFD, HH, 1);
    add(gW1, g1t_h, g1t_l, HH, HH, 1);
    add(node_feats, nf_h, nf_l, NN, 64, 0);
    tab.n = ne;

    conv_kernel<<<blk, 256>>>(tab);
    wa_kernel<<<LL, 64>>>(We, be, gata);
    ce_kernel<<<EE / 256, 256>>>(edge_feats);

    dim3 gH(HH / 128, NN / 128);     // (2, 128)
    dim3 gQKV(768 / 128, NN / 128);  // (6, 128)
    dim3 gF(FFD / 128, NN / 128);    // (4, 128)

    gemm_tc<<<gH, 256, SMEM_GEMM>>>(nf_h, nf_l, wnt_h, wnt_l, bn, h_p, h_h, h_l,
                                    NN, 64, HH, 0);

    for (int l = 0; l < LL; l++) {
        gemm_tc<<<gH, 256, SMEM_GEMM>>>(h_h, h_l, gwt_h + (size_t)l * HH * HH,
                                        gwt_l + (size_t)l * HH * HH, nullptr,
                                        m_p, nullptr, nullptr, NN, HH, HH, 0);
        gat_layer_kernel<<<GB, 256, GATSM>>>(dst, ce_p + (size_t)l * EE,
                                             gata, glng, glnb, l);
    }

    gemm_tc<<<gQKV, 256, SMEM_GEMM>>>(h_h, h_l, qkvt_h, qkvt_l, nullptr, qkv_p,
                                      nullptr, nullptr, NN, HH, 768, 0);
    attn_kernel<<<dim3(NHEADS, GB), 256>>>();
    ln_kernel<<<NN, 256>>>(o_p, h_p, alng, alnb, h_p, h_h, h_l, 1e-6f);

    gemm_tc<<<gF, 256, SMEM_GEMM>>>(h_h, h_l, f1t_h, f1t_l, fb1, nullptr,
                                    ff_h, ff_l, NN, HH, FFD, 2);
    gemm_tc<<<gH, 256, SMEM_GEMM>>>(ff_h, ff_l, f2t_h, f2t_l, fb2, m_p,
                                    nullptr, nullptr, NN, FFD, HH, 0);
    ln_kernel<<<NN, 256>>>(h_p, m_p, flng, flnb, h_p, h_h, h_l, 1e-6f);

    gemm_tc<<<gH, 256, SMEM_GEMM>>>(h_h, h_l, g1t_h, g1t_l, gb1, m_p,
                                    nullptr, nullptr, NN, HH, HH, 1);
    gvec_kernel<<<NN / 8, 256>>>(gW2, gb2);
    readout_kernel<<<GB, 256>>>(out);

    (void)in_sizes; (void)n_in; (void)out_size;
}